// round 12
// baseline (speedup 1.0000x reference)
#include <cuda_runtime.h>
#include <cuda_fp16.h>
#include <math.h>

#define NN 100000
#define EE 3200000
#define NB 98   // ceil(NN/1024)
#define SENT 0x80000000

typedef unsigned long long u64;

__device__ __forceinline__ u64 pk(float a, float b) {
    u64 r; asm("mov.b64 %0,{%1,%2};" : "=l"(r) : "f"(a), "f"(b)); return r;
}
__device__ __forceinline__ void upk(u64 v, float& a, float& b) {
    asm("mov.b64 {%0,%1},%2;" : "=f"(a), "=f"(b) : "l"(v));
}
__device__ __forceinline__ void ffma2(u64& d, u64 a, u64 b) {
    asm("fma.rn.f32x2 %0,%1,%2,%0;" : "+l"(d) : "l"(a), "l"(b));
}

// ---------------- device scratch ----------------
// unified GRU input stream, u64-paired, [row][n]:
//   rows 0-15: H  16-31: mean_to  32-47: mean_fr  48-63: lp-ReLU  64-65: x  66-67: zero pad
__device__ __align__(16) u64 g_S[68 * NN];
__device__ __align__(16) __half g_PdtH[NN * 32];
__device__ __align__(16) __half g_PdfH[NN * 32];
__device__ __align__(16) __half g_PstH[NN * 32];
__device__ __align__(16) __half g_PsfH[NN * 32];
__device__ int   g_cnt_to[NN];
__device__ int   g_cnt_fr[NN];
__device__ float g_selfsum[NN];
__device__ float g_loss[4];

// CSR
__device__ int g_rowp_to[NN + 1];
__device__ int g_rowp_fr[NN + 1];
__device__ int g_cur_to[NN];
__device__ int g_cur_fr[NN];
__device__ __align__(16) u64 g_pay_to[EE];
__device__ __align__(16) u64 g_pay_fr[EE];
__device__ int g_flag[2 * NB];
__device__ int g_done;

// packed/folded weights
__device__ __align__(16) u64   g_Gp[132 * 48];   // [j][qp] = (Gfold(2qp,j), Gfold(2qp+1,j))
__device__ float g_bias[96];
__device__ float g_cto[96];
__device__ float g_cfr[96];
__device__ __align__(16) u64 g_ewp[96];          // [dir][row(wa0,wa1,b)][k] float-pairs

// ---------------- init ----------------
__global__ void k_init() {
    int t = blockIdx.x * blockDim.x + threadIdx.x;
    int nt = gridDim.x * blockDim.x;
    __half hz = __float2half(0.f);
    for (int i = t; i < 16 * NN; i += nt) g_S[i] = 0ull;   // H rows
    for (int i = t; i < 32 * NN; i += nt) {
        g_PdtH[i] = hz; g_PdfH[i] = hz; g_PstH[i] = hz; g_PsfH[i] = hz;
    }
    for (int i = t; i < NN; i += nt) {
        g_cnt_to[i] = 0; g_cnt_fr[i] = 0; g_selfsum[i] = 0.f;
    }
    for (int i = t; i < 2 * NB; i += nt) g_flag[i] = (int)SENT;
    if (t == 0) g_done = 0;
    if (t < 4) g_loss[t] = 0.f;
}

// ---------------- count + weight folding, one kernel ----------------
__device__ __forceinline__ float gfold(int q, int c, const float* Wih,
                                       const float* toW2, const float* frW2,
                                       const float* lpW2) {
    if (c < 32) return Wih[q * 131 + c];
    if (c < 64) {
        float v = 0.f;
        for (int i = 0; i < 32; i++) v += Wih[q * 131 + 32 + i] * toW2[i * 32 + (c - 32)];
        return v;
    }
    if (c < 96) {
        float v = 0.f;
        for (int i = 0; i < 32; i++) v += Wih[q * 131 + 64 + i] * frW2[i * 32 + (c - 64)];
        return v;
    }
    if (c < 128) {
        float v = 0.f;
        for (int i = 0; i < 32; i++) v += Wih[q * 131 + 96 + i] * lpW2[i * 32 + (c - 96)];
        return v;
    }
    if (c < 131) return Wih[q * 131 + 128 + (c - 128)];
    return 0.f;
}

__global__ void k_cp(const int* __restrict__ ei, const float* __restrict__ ea,
                     const float* __restrict__ Wih, const float* __restrict__ bih,
                     const float* __restrict__ bhh,
                     const float* __restrict__ toW2, const float* __restrict__ tob2,
                     const float* __restrict__ frW2, const float* __restrict__ frb2,
                     const float* __restrict__ lpW2, const float* __restrict__ lpb2,
                     const float* __restrict__ toW1, const float* __restrict__ tob1,
                     const float* __restrict__ frW1, const float* __restrict__ frb1) {
    int t = blockIdx.x * blockDim.x + threadIdx.x;
    int nt = gridDim.x * blockDim.x;
    // edge counting
    if (t < EE) {
        int s = ei[t];
        int d = ei[EE + t];
        if (s != d) {
            atomicAdd(&g_cnt_to[d], 1);
            atomicAdd(&g_cnt_fr[s], 1);
        } else {
            atomicAdd(&g_selfsum[s], ea[2 * t]);
        }
    }
    // folded GRU weights, directly paired
    for (int idx = t; idx < 132 * 48; idx += nt) {
        int j = idx / 48, qp = idx - j * 48;
        g_Gp[idx] = pk(gfold(2 * qp, j, Wih, toW2, frW2, lpW2),
                       gfold(2 * qp + 1, j, Wih, toW2, frW2, lpW2));
    }
    for (int q = t; q < 96; q += nt) {
        float b = bih[q], ct = 0.f, cf = 0.f;
        for (int i = 0; i < 32; i++) {
            b  += Wih[q * 131 + 96 + i] * lpb2[i];
            ct += Wih[q * 131 + 32 + i] * tob2[i];
            cf += Wih[q * 131 + 64 + i] * frb2[i];
        }
        if (q < 64) b += bhh[q];
        g_bias[q] = b; g_cto[q] = ct; g_cfr[q] = cf;
    }
    for (int i = t; i < 96; i += nt) {
        int dir = i / 48, r = (i % 48) / 16, k = i & 15;
        const float* W1 = dir ? frW1 : toW1;
        const float* b1 = dir ? frb1 : tob1;
        float v0, v1;
        if (r < 2) { v0 = W1[(2 * k) * 66 + 64 + r]; v1 = W1[(2 * k + 1) * 66 + 64 + r]; }
        else       { v0 = b1[2 * k];                 v1 = b1[2 * k + 1]; }
        g_ewp[i] = pk(v0, v1);
    }
}

// ---------------- one-kernel CSR build: scan (lookback) + sync + scatter + lp0 ----------------
__global__ __launch_bounds__(1024) void k_scansc(const int* __restrict__ ei,
                                                 const float* __restrict__ ea,
                                                 const float* __restrict__ lpW1,
                                                 const float* __restrict__ lpb1,
                                                 const float* __restrict__ x) {
    __shared__ int sh[1024];
    __shared__ int sred[32];
    __shared__ int sprev_sh;
    int arr = blockIdx.y, bx = blockIdx.x, tid = threadIdx.x;
    int i = bx * 1024 + tid;
    const int* cnt = arr ? g_cnt_fr : g_cnt_to;
    int* rowp = arr ? g_rowp_fr : g_rowp_to;
    int* cur  = arr ? g_cur_fr  : g_cur_to;

    int v = (i < NN) ? cnt[i] : 0;
    sh[tid] = v;
    __syncthreads();
#pragma unroll
    for (int off = 1; off < 1024; off <<= 1) {
        int t2 = (tid >= off) ? sh[tid - off] : 0;
        __syncthreads();
        sh[tid] += t2;
        __syncthreads();
    }
    int total = sh[1023];
    if (tid == 0) atomicExch(&g_flag[arr * NB + bx], total);   // publish own total

    // full lookback: sum all previous block totals in parallel
    int p = 0;
    if (tid < bx) {
        int w;
        do { w = atomicAdd(&g_flag[arr * NB + tid], 0); } while (w == (int)SENT);
        p = w;
    }
#pragma unroll
    for (int o = 16; o; o >>= 1) p += __shfl_down_sync(0xffffffffu, p, o);
    if ((tid & 31) == 0) sred[tid >> 5] = p;
    __syncthreads();
    if (tid == 0) {
        int s = 0;
#pragma unroll
        for (int k = 0; k < 32; k++) s += sred[k];
        sprev_sh = s;
    }
    __syncthreads();
    int base = sprev_sh;

    if (i < NN) {
        int ex = base + sh[tid] - v;
        rowp[i] = ex;
        cur[i] = ex;
    }
    if (tid == 1023 && bx == NB - 1) rowp[NN] = base + total;

    // lp0 + x rows (H = 0 at step 0)
    if (arr == 0 && i < NN) {
        float lc = -g_selfsum[i];
#pragma unroll
        for (int k = 0; k < 16; k++) {
            float v0 = fmaxf(__ldg(&lpb1[2 * k])     + __ldg(&lpW1[(2 * k) * 65 + 64]) * lc, 0.f);
            float v1 = fmaxf(__ldg(&lpb1[2 * k + 1]) + __ldg(&lpW1[(2 * k + 1) * 65 + 64]) * lc, 0.f);
            g_S[(48 + k) * NN + i] = pk(v0, v1);
        }
        float x0 = __ldg(&x[i * 3]), x1 = __ldg(&x[i * 3 + 1]), x2 = __ldg(&x[i * 3 + 2]);
        g_S[64 * NN + i] = pk(x0, x1);
        g_S[65 * NN + i] = pk(x2, 0.f);
    }

    // device-wide sync (196 blocks all resident: 1024 thr, ~4KB smem -> 2 blocks/SM x 148)
    __syncthreads();
    if (tid == 0) {
        __threadfence();
        atomicAdd(&g_done, 1);
        while (atomicAdd(&g_done, 0) < 2 * NB) { }
    }
    __syncthreads();

    // scatter phase: grid-stride over all edges
    int gtid = (arr * NB + bx) * 1024 + tid;
    for (int e = gtid; e < EE; e += 2 * NB * 1024) {
        int s = ei[e];
        int d = ei[EE + e];
        if (s == d) continue;
        __half2 eh = __floats2half2_rn(ea[2 * e], ea[2 * e + 1]);
        unsigned ehu = *(unsigned*)&eh;
        u64 hi = ((u64)ehu) << 32;
        int p1 = atomicAdd(&g_cur_to[d], 1);
        g_pay_to[p1] = hi | (unsigned)s;
        int p2 = atomicAdd(&g_cur_fr[s], 1);
        g_pay_fr[p2] = hi | (unsigned)d;
    }
}

// ---------------- edge pass: 16-lane group per node, payload double-buffered ----------------
__global__ __launch_bounds__(256) void k_pass() {
    int gid = (blockIdx.x * 256 + threadIdx.x) >> 4;
    int k = threadIdx.x & 15;
    int dir = gid >= NN;
    int n = gid - dir * NN;
    if (n >= NN) return;

    const int*    rowp = dir ? g_rowp_fr : g_rowp_to;
    const u64*    pay  = dir ? g_pay_fr  : g_pay_to;
    const __half* stat = dir ? g_PsfH    : g_PdtH;
    const __half* gat  = dir ? g_PdfH    : g_PstH;
    u64*          outp = &g_S[(16 + dir * 16 + k) * NN];

    float wa00, wa01, wa10, wa11, b0, b1;
    upk(__ldg(&g_ewp[dir * 48 + k]),      wa00, wa01);
    upk(__ldg(&g_ewp[dir * 48 + 16 + k]), wa10, wa11);
    upk(__ldg(&g_ewp[dir * 48 + 32 + k]), b0, b1);

    int beg = __ldg(&rowp[n]);
    int end = __ldg(&rowp[n + 1]);
    float2 sf = __half22float2(*(const __half2*)&stat[n * 32 + 2 * k]);
    float base0 = sf.x + b0, base1 = sf.y + b1;
    float acc0 = 0.f, acc1 = 0.f;

    int e = beg;
    if ((e & 1) && e < end) {           // peel to 16B alignment
        u64 p = __ldg(&pay[e]);
        int idx = (int)(unsigned)p;
        unsigned ehu = (unsigned)(p >> 32);
        float2 eaf = __half22float2(*(__half2*)&ehu);
        float2 g = __half22float2(*(const __half2*)&gat[idx * 32 + 2 * k]);
        acc0 += fmaxf(base0 + g.x + eaf.x * wa00 + eaf.y * wa10, 0.f);
        acc1 += fmaxf(base1 + g.y + eaf.x * wa01 + eaf.y * wa11, 0.f);
        e++;
    }
    if (e + 1 < end) {                  // pipelined pairs: prefetch next payload
        uint4 cur = __ldg((const uint4*)&pay[e]);
        e += 2;
        for (; e + 1 < end; e += 2) {
            uint4 nx = __ldg((const uint4*)&pay[e]);
            float2 ea0 = __half22float2(*(__half2*)&cur.y);
            float2 ea1 = __half22float2(*(__half2*)&cur.w);
            float2 g0 = __half22float2(*(const __half2*)&gat[(int)cur.x * 32 + 2 * k]);
            float2 g1 = __half22float2(*(const __half2*)&gat[(int)cur.z * 32 + 2 * k]);
            acc0 += fmaxf(base0 + g0.x + ea0.x * wa00 + ea0.y * wa10, 0.f);
            acc1 += fmaxf(base1 + g0.y + ea0.x * wa01 + ea0.y * wa11, 0.f);
            acc0 += fmaxf(base0 + g1.x + ea1.x * wa00 + ea1.y * wa10, 0.f);
            acc1 += fmaxf(base1 + g1.y + ea1.x * wa01 + ea1.y * wa11, 0.f);
            cur = nx;
        }
        float2 ea0 = __half22float2(*(__half2*)&cur.y);
        float2 ea1 = __half22float2(*(__half2*)&cur.w);
        float2 g0 = __half22float2(*(const __half2*)&gat[(int)cur.x * 32 + 2 * k]);
        float2 g1 = __half22float2(*(const __half2*)&gat[(int)cur.z * 32 + 2 * k]);
        acc0 += fmaxf(base0 + g0.x + ea0.x * wa00 + ea0.y * wa10, 0.f);
        acc1 += fmaxf(base1 + g0.y + ea0.x * wa01 + ea0.y * wa11, 0.f);
        acc0 += fmaxf(base0 + g1.x + ea1.x * wa00 + ea1.y * wa10, 0.f);
        acc1 += fmaxf(base1 + g1.y + ea1.x * wa01 + ea1.y * wa11, 0.f);
    }
    if (e < end) {
        u64 p = __ldg(&pay[e]);
        int idx = (int)(unsigned)p;
        unsigned ehu = (unsigned)(p >> 32);
        float2 eaf = __half22float2(*(__half2*)&ehu);
        float2 g = __half22float2(*(const __half2*)&gat[idx * 32 + 2 * k]);
        acc0 += fmaxf(base0 + g.x + eaf.x * wa00 + eaf.y * wa10, 0.f);
        acc1 += fmaxf(base1 + g.y + eaf.x * wa01 + eaf.y * wa11, 0.f);
    }
    int cnt = end - beg;
    float rt = cnt > 0 ? 1.f / (float)cnt : 0.f;
    outp[n] = pk(acc0 * rt, acc1 * rt);   // mean, pre-scaled
}

// ---------------- k_gru: output-stationary GEMV, coalesced row stream ----------------
__device__ __forceinline__ void consume(u64* acc, const u64* sGp, int j2, u64 c) {
    float v0, v1; upk(c, v0, v1);
    u64 s0 = pk(v0, v0), s1 = pk(v1, v1);
    const u64* w0p = &sGp[(2 * j2) * 48];
    const u64* w1p = w0p + 48;
#pragma unroll
    for (int qb = 0; qb < 24; qb++) {
        ulonglong2 w = *(const ulonglong2*)&w0p[qb * 2];
        ffma2(acc[qb * 2], w.x, s0);
        ffma2(acc[qb * 2 + 1], w.y, s0);
    }
#pragma unroll
    for (int qb = 0; qb < 24; qb++) {
        ulonglong2 w = *(const ulonglong2*)&w1p[qb * 2];
        ffma2(acc[qb * 2], w.x, s1);
        ffma2(acc[qb * 2 + 1], w.y, s1);
    }
}

__global__ __launch_bounds__(128, 3) void k_gru(const float* __restrict__ bhh) {
    extern __shared__ u64 smu[];
    u64*   sGp  = smu;                       // 6336 u64
    float* sb   = (float*)(smu + 6336);      // 96
    float* sct  = sb + 96;                   // 96
    float* scf  = sct + 96;                  // 96
    float* sbhn = scf + 96;                  // 32

    for (int i = threadIdx.x; i < 6336; i += 128) sGp[i] = g_Gp[i];
    for (int i = threadIdx.x; i < 96; i += 128) {
        sb[i] = g_bias[i]; sct[i] = g_cto[i]; scf[i] = g_cfr[i];
    }
    if (threadIdx.x < 32) sbhn[threadIdx.x] = bhh[64 + threadIdx.x];
    __syncthreads();

    int n = blockIdx.x * 128 + threadIdx.x;
    if (n >= NN) return;

    float ft = (__ldg(&g_cnt_to[n]) > 0) ? 1.f : 0.f;
    float ff = (__ldg(&g_cnt_fr[n]) > 0) ? 1.f : 0.f;

    u64 acc[48];
#pragma unroll
    for (int qp = 0; qp < 48; qp++) {
        int q0 = 2 * qp, q1 = q0 + 1;
        acc[qp] = pk(sb[q0] + ft * sct[q0] + ff * scf[q0],
                     sb[q1] + ft * sct[q1] + ff * scf[q1]);
    }

    // stream 66 coalesced u64 rows, branch-free prefetch depth 2 (rows 66/67 are zero pad)
    u64 c0 = __ldg(&g_S[n]);
    u64 c1 = __ldg(&g_S[NN + n]);
    for (int j2 = 0; j2 < 66; j2++) {
        u64 cur = c0;
        c0 = c1;
        c1 = __ldg(&g_S[(j2 + 2) * NN + n]);
        consume(acc, sGp, j2, cur);
    }

#pragma unroll
    for (int i = 0; i < 16; i++) {
        float aR0, aR1, aZ0, aZ1, aN0, aN1;
        upk(acc[i], aR0, aR1);
        upk(acc[16 + i], aZ0, aZ1);
        upk(acc[32 + i], aN0, aN1);
        int q0 = 2 * i, q1 = q0 + 1;
        float r0 = 1.f / (1.f + __expf(-aR0));
        float r1 = 1.f / (1.f + __expf(-aR1));
        float z0 = 1.f / (1.f + __expf(-aZ0));
        float z1 = 1.f / (1.f + __expf(-aZ1));
        float tn0 = aN0 + r0 * sbhn[q0];
        float tn1 = aN1 + r1 * sbhn[q1];
        float th0 = 2.f / (1.f + __expf(-2.f * tn0)) - 1.f;
        float th1 = 2.f / (1.f + __expf(-2.f * tn1)) - 1.f;
        float h0, h1; upk(g_S[i * NN + n], h0, h1);
        h0 += 0.5f * (1.f - z0) * th0;   // ALPHA = 0.5
        h1 += 0.5f * (1.f - z1) * th1;
        g_S[i * NN + n] = pk(h0, h1);
    }
}

// ---------------- k_post: 4 parallel slices ----------------
// y=0: decode+loss   y=1: proj Pdt/Pdf   y=2: proj Pst/Psf   y=3: lp->rows 48-63
__global__ __launch_bounds__(128) void k_post(
        const float* __restrict__ toW1, const float* __restrict__ frW1,
        const float* __restrict__ lpW1, const float* __restrict__ lpb1,
        const float* __restrict__ dec1, const float* __restrict__ decb1,
        const float* __restrict__ dec2, const float* __restrict__ decb2,
        const float* __restrict__ y, float* __restrict__ outF, int loss_idx) {
    __shared__ float sW[2048];
    __shared__ float sD2[64];
    __shared__ float sDb1[32];
    __shared__ float sDb2[2];

    int slice = blockIdx.y;
    if (slice == 0) {
        for (int i = threadIdx.x; i < 1024; i += 128) sW[i] = dec1[i];
        if (threadIdx.x < 64) sD2[threadIdx.x] = dec2[threadIdx.x];
        if (threadIdx.x < 32) sDb1[threadIdx.x] = decb1[threadIdx.x];
        if (threadIdx.x < 2)  sDb2[threadIdx.x] = decb2[threadIdx.x];
    } else if (slice <= 2) {
        int half = slice - 1;
        for (int i = threadIdx.x; i < 2048; i += 128) {
            int m = half * 2 + (i >> 10), r = i & 1023, ii = r >> 5, j = r & 31;
            float v;
            if (m == 0)      v = toW1[ii * 66 + j];        // Pdt
            else if (m == 1) v = frW1[ii * 66 + 32 + j];   // Pdf
            else if (m == 2) v = toW1[ii * 66 + 32 + j];   // Pst
            else             v = frW1[ii * 66 + j];        // Psf
            sW[i] = v;
        }
    } else {
        for (int i = threadIdx.x; i < 1152; i += 128) {
            int tq = i / 36, c = i - tq * 36;
            float v = 0.f;
            if (c < 32)       v = lpW1[tq * 65 + c] + lpW1[tq * 65 + 32 + c];
            else if (c == 32) v = lpW1[tq * 65 + 64];
            sW[i] = v;
        }
        if (threadIdx.x < 32) sDb1[threadIdx.x] = lpb1[threadIdx.x];
    }
    __syncthreads();

    int n = blockIdx.x * 128 + threadIdx.x;
    if (n >= NN) return;

    u64 vHp[16];
#pragma unroll
    for (int k = 0; k < 16; k++) vHp[k] = __ldg(&g_S[k * NN + n]);

    if (slice == 0) {
        float F0 = sDb2[0], F1 = sDb2[1];
        for (int i = 0; i < 32; i++) {
            u64 acc = pk(sDb1[i], 0.f);
#pragma unroll
            for (int j4 = 0; j4 < 8; j4++) {
                ulonglong2 w = *(const ulonglong2*)&sW[i * 32 + j4 * 4];
                ffma2(acc, w.x, vHp[j4 * 2]);
                ffma2(acc, w.y, vHp[j4 * 2 + 1]);
            }
            float lo, hi; upk(acc, lo, hi);
            float a = fmaxf(lo + hi, 0.f);
            F0 += sD2[i] * a;
            F1 += sD2[32 + i] * a;
        }
        float d0 = F0 - y[n * 2], d1 = F1 - y[n * 2 + 1];
        float sse = d0 * d0 + d1 * d1;
        if (outF) { outF[n * 2] = F0; outF[n * 2 + 1] = F1; }
#pragma unroll
        for (int o = 16; o; o >>= 1) sse += __shfl_down_sync(0xffffffffu, sse, o);
        if ((threadIdx.x & 31) == 0) atomicAdd(&g_loss[loss_idx], sse);
    } else if (slice <= 2) {
        int half = slice - 1;
        __half* outA = half ? g_PstH : g_PdtH;
        __half* outB = half ? g_PsfH : g_PdfH;
        for (int i4 = 0; i4 < 8; i4++) {
            u64 A[8];
#pragma unroll
            for (int t = 0; t < 8; t++) A[t] = 0ull;
#pragma unroll
            for (int j4 = 0; j4 < 8; j4++) {
                u64 vlo = vHp[j4 * 2], vhi = vHp[j4 * 2 + 1];
#pragma unroll
                for (int mm = 0; mm < 2; mm++) {
#pragma unroll
                    for (int ii = 0; ii < 4; ii++) {
                        ulonglong2 w = *(const ulonglong2*)&sW[mm * 1024 + (i4 * 4 + ii) * 32 + j4 * 4];
                        ffma2(A[mm * 4 + ii], w.x, vlo);
                        ffma2(A[mm * 4 + ii], w.y, vhi);
                    }
                }
            }
            __half2 hA01, hA23, hB01, hB23;
            float l0, h0, l1, h1, l2, h2, l3, h3;
            upk(A[0], l0, h0); upk(A[1], l1, h1); upk(A[2], l2, h2); upk(A[3], l3, h3);
            hA01 = __floats2half2_rn(l0 + h0, l1 + h1);
            hA23 = __floats2half2_rn(l2 + h2, l3 + h3);
            upk(A[4], l0, h0); upk(A[5], l1, h1); upk(A[6], l2, h2); upk(A[7], l3, h3);
            hB01 = __floats2half2_rn(l0 + h0, l1 + h1);
            hB23 = __floats2half2_rn(l2 + h2, l3 + h3);
            uint2 stA, stB;
            stA.x = *(unsigned*)&hA01; stA.y = *(unsigned*)&hA23;
            stB.x = *(unsigned*)&hB01; stB.y = *(unsigned*)&hB23;
            *(uint2*)&outA[n * 32 + i4 * 4] = stA;
            *(uint2*)&outB[n * 32 + i4 * 4] = stB;
        }
    } else {
        float lc = -g_selfsum[n];
#pragma unroll
        for (int i2 = 0; i2 < 16; i2++) {
            int i0 = 2 * i2;
            u64 acc0 = pk(sDb1[i0]     + sW[i0 * 36 + 32] * lc, 0.f);
            u64 acc1 = pk(sDb1[i0 + 1] + sW[(i0 + 1) * 36 + 32] * lc, 0.f);
#pragma unroll
            for (int j4 = 0; j4 < 8; j4++) {
                ulonglong2 w0 = *(const ulonglong2*)&sW[i0 * 36 + j4 * 4];
                ulonglong2 w1 = *(const ulonglong2*)&sW[(i0 + 1) * 36 + j4 * 4];
                ffma2(acc0, w0.x, vHp[j4 * 2]); ffma2(acc0, w0.y, vHp[j4 * 2 + 1]);
                ffma2(acc1, w1.x, vHp[j4 * 2]); ffma2(acc1, w1.y, vHp[j4 * 2 + 1]);
            }
            float a0, b0, a1, b1;
            upk(acc0, a0, b0); upk(acc1, a1, b1);
            g_S[(48 + i2) * NN + n] = pk(fmaxf(a0 + b0, 0.f), fmaxf(a1 + b1, 0.f));
        }
    }
}

// ---------------- finalize losses ----------------
__global__ void k_final(float* __restrict__ out) {
    if (blockIdx.x == 0 && threadIdx.x == 0) {
        float inv = 1.f / (2.f * (float)NN);
        float l0 = g_loss[0] * inv;
        float l1 = g_loss[1] * inv;
        float l2 = g_loss[2] * inv;
        float l3 = g_loss[3] * inv;
        out[200000] = 0.729f * l0 + 0.81f * l1 + 0.9f * l2 + l3;
        out[200001] = l0; out[200002] = l1; out[200003] = l2; out[200004] = l3;
    }
}

// ---------------- launch ----------------
extern "C" void kernel_launch(void* const* d_in, const int* in_sizes, int n_in,
                              void* d_out, int out_size) {
    const float* x    = (const float*)d_in[0];
    const float* y    = (const float*)d_in[1];
    const int*   ei   = (const int*)d_in[2];
    const float* ea   = (const float*)d_in[3];
    const float* toW1 = (const float*)d_in[4];
    const float* tob1 = (const float*)d_in[5];
    const float* toW2 = (const float*)d_in[6];
    const float* tob2 = (const float*)d_in[7];
    const float* frW1 = (const float*)d_in[8];
    const float* frb1 = (const float*)d_in[9];
    const float* frW2 = (const float*)d_in[10];
    const float* frb2 = (const float*)d_in[11];
    const float* lpW1 = (const float*)d_in[12];
    const float* lpb1 = (const float*)d_in[13];
    const float* lpW2 = (const float*)d_in[14];
    const float* lpb2 = (const float*)d_in[15];
    const float* Wih  = (const float*)d_in[16];
    const float* bih  = (const float*)d_in[17];
    // d_in[18] = gru_Whh (unused: h0 = 0)
    const float* bhh  = (const float*)d_in[19];
    const float* dec1 = (const float*)d_in[20];
    const float* decb1= (const float*)d_in[21];
    const float* dec2 = (const float*)d_in[22];
    const float* decb2= (const float*)d_in[23];
    float* out = (float*)d_out;

    const int gru_smem = 6336 * 8 + 320 * 4;   // 51968 bytes
    cudaFuncSetAttribute(k_gru, cudaFuncAttributeMaxDynamicSharedMemorySize, gru_smem);

    k_init<<<1024, 256>>>();                                        // launch 0
    k_cp<<<(EE + 255) / 256, 256>>>(ei, ea, Wih, bih, bhh,          // launch 1
                                    toW2, tob2, frW2, frb2, lpW2, lpb2,
                                    toW1, tob1, frW1, frb1);
    k_scansc<<<dim3(NB, 2), 1024>>>(ei, ea, lpW1, lpb1, x);         // launch 2

    int nblk = (NN + 127) / 128;
    for (int step = 0; step < 4; step++) {
        int do_proj = (step < 3) ? 1 : 0;
        k_pass<<<12500, 256>>>();                                   // step0 -> launch 3 (profiled)
        k_gru<<<nblk, 128, gru_smem>>>(bhh);
        dim3 pgrid(nblk, do_proj ? 4 : 1);
        k_post<<<pgrid, 128>>>(toW1, frW1, lpW1, lpb1, dec1, decb1, dec2, decb2, y,
                               (step == 3) ? out : nullptr, step);
    }
    k_final<<<1, 32>>>(out);
}

// round 13
// speedup vs baseline: 1.1306x; 1.1306x over previous
#include <cuda_runtime.h>
#include <cuda_fp16.h>
#include <math.h>

#define NN 100000
#define EE 3200000
#define NB 98   // ceil(NN/1024)

typedef unsigned long long u64;

__device__ __forceinline__ u64 pk(float a, float b) {
    u64 r; asm("mov.b64 %0,{%1,%2};" : "=l"(r) : "f"(a), "f"(b)); return r;
}
__device__ __forceinline__ void upk(u64 v, float& a, float& b) {
    asm("mov.b64 {%0,%1},%2;" : "=f"(a), "=f"(b) : "l"(v));
}
__device__ __forceinline__ void ffma2(u64& d, u64 a, u64 b) {
    asm("fma.rn.f32x2 %0,%1,%2,%0;" : "+l"(d) : "l"(a), "l"(b));
}
__device__ __forceinline__ void upk2h(u64 v, __half2& a, __half2& b) {
    unsigned lo, hi;
    asm("mov.b64 {%0,%1},%2;" : "=r"(lo), "=r"(hi) : "l"(v));
    a = *(__half2*)&lo; b = *(__half2*)&hi;
}

// ---------------- device scratch ----------------
// unified GRU input stream, u64-paired, [row][n]:
//   rows 0-15: H  16-31: mean_to  32-47: mean_fr  48-63: lp-ReLU  64-65: x  66-67: zero pad
__device__ __align__(16) u64 g_S[68 * NN];
__device__ __align__(16) __half g_PdtH[NN * 32];
__device__ __align__(16) __half g_PdfH[NN * 32];
__device__ __align__(16) __half g_PstH[NN * 32];
__device__ __align__(16) __half g_PsfH[NN * 32];
__device__ int   g_cnt_to[NN];
__device__ int   g_cnt_fr[NN];
__device__ float g_selfsum[NN];
__device__ float g_loss[4];

// CSR
__device__ int g_rowp_to[NN + 1];
__device__ int g_rowp_fr[NN + 1];
__device__ int g_cur_to[NN];
__device__ int g_cur_fr[NN];
__device__ __align__(16) u64 g_pay_to[EE];
__device__ __align__(16) u64 g_pay_fr[EE];
__device__ int g_flag[2 * NB];   // 0 = unpublished; else block_total + 1
__device__ int g_done;

// packed/folded weights
__device__ __align__(16) u64 g_Gp[132 * 48];   // [j][qp] = (Gfold(2qp,j), Gfold(2qp+1,j))
__device__ float g_bias[96];
__device__ float g_cto[96];
__device__ float g_cfr[96];
__device__ __align__(16) u64 g_ewh[48];        // half2x2 edge weights: [dir][row(wa0,wa1,b)][k4]

// ---------------- count + weight folding, one kernel ----------------
__device__ __forceinline__ float gfold(int q, int c, const float* Wih,
                                       const float* toW2, const float* frW2,
                                       const float* lpW2) {
    if (c < 32) return Wih[q * 131 + c];
    if (c < 64) {
        float v = 0.f;
        for (int i = 0; i < 32; i++) v += Wih[q * 131 + 32 + i] * toW2[i * 32 + (c - 32)];
        return v;
    }
    if (c < 96) {
        float v = 0.f;
        for (int i = 0; i < 32; i++) v += Wih[q * 131 + 64 + i] * frW2[i * 32 + (c - 64)];
        return v;
    }
    if (c < 128) {
        float v = 0.f;
        for (int i = 0; i < 32; i++) v += Wih[q * 131 + 96 + i] * lpW2[i * 32 + (c - 96)];
        return v;
    }
    if (c < 131) return Wih[q * 131 + 128 + (c - 128)];
    return 0.f;
}

__global__ void k_cp(const int* __restrict__ ei, const float* __restrict__ ea,
                     const float* __restrict__ Wih, const float* __restrict__ bih,
                     const float* __restrict__ bhh,
                     const float* __restrict__ toW2, const float* __restrict__ tob2,
                     const float* __restrict__ frW2, const float* __restrict__ frb2,
                     const float* __restrict__ lpW2, const float* __restrict__ lpb2,
                     const float* __restrict__ toW1, const float* __restrict__ tob1,
                     const float* __restrict__ frW1, const float* __restrict__ frb1) {
    int t = blockIdx.x * blockDim.x + threadIdx.x;
    int nt = gridDim.x * blockDim.x;
    // edge counting
    if (t < EE) {
        int s = ei[t];
        int d = ei[EE + t];
        if (s != d) {
            atomicAdd(&g_cnt_to[d], 1);
            atomicAdd(&g_cnt_fr[s], 1);
        } else {
            atomicAdd(&g_selfsum[s], ea[2 * t]);
        }
    }
    // folded GRU weights, directly paired
    for (int idx = t; idx < 132 * 48; idx += nt) {
        int j = idx / 48, qp = idx - j * 48;
        g_Gp[idx] = pk(gfold(2 * qp, j, Wih, toW2, frW2, lpW2),
                       gfold(2 * qp + 1, j, Wih, toW2, frW2, lpW2));
    }
    for (int q = t; q < 96; q += nt) {
        float b = bih[q], ct = 0.f, cf = 0.f;
        for (int i = 0; i < 32; i++) {
            b  += Wih[q * 131 + 96 + i] * lpb2[i];
            ct += Wih[q * 131 + 32 + i] * tob2[i];
            cf += Wih[q * 131 + 64 + i] * frb2[i];
        }
        if (q < 64) b += bhh[q];
        g_bias[q] = b; g_cto[q] = ct; g_cfr[q] = cf;
    }
    // half2 edge weights: [dir][r(wa0,wa1,b)][k] covering cols 4k..4k+3
    for (int i = t; i < 48; i += nt) {
        int dir = i / 24, r = (i % 24) / 8, k = i & 7;
        const float* W1 = dir ? frW1 : toW1;
        const float* b1 = dir ? frb1 : tob1;
        float v[4];
        for (int c = 0; c < 4; c++) {
            int j = 4 * k + c;
            v[c] = (r < 2) ? W1[j * 66 + 64 + r] : b1[j];
        }
        __half2 a = __floats2half2_rn(v[0], v[1]);
        __half2 b2 = __floats2half2_rn(v[2], v[3]);
        unsigned ua = *(unsigned*)&a, ub = *(unsigned*)&b2;
        g_ewh[i] = (((u64)ub) << 32) | ua;
    }
}

// ---------------- one-kernel CSR build: scan (lookback) + sync + scatter + lp0 ----------------
__global__ __launch_bounds__(1024) void k_scansc(const int* __restrict__ ei,
                                                 const float* __restrict__ ea,
                                                 const float* __restrict__ lpW1,
                                                 const float* __restrict__ lpb1,
                                                 const float* __restrict__ x) {
    __shared__ int sh[1024];
    __shared__ int sred[32];
    __shared__ int sprev_sh;
    int arr = blockIdx.y, bx = blockIdx.x, tid = threadIdx.x;
    int i = bx * 1024 + tid;
    const int* cnt = arr ? g_cnt_fr : g_cnt_to;
    int* rowp = arr ? g_rowp_fr : g_rowp_to;
    int* cur  = arr ? g_cur_fr  : g_cur_to;

    int v = (i < NN) ? cnt[i] : 0;
    sh[tid] = v;
    __syncthreads();
#pragma unroll
    for (int off = 1; off < 1024; off <<= 1) {
        int t2 = (tid >= off) ? sh[tid - off] : 0;
        __syncthreads();
        sh[tid] += t2;
        __syncthreads();
    }
    int total = sh[1023];
    if (tid == 0) atomicExch(&g_flag[arr * NB + bx], total + 1);   // publish (0 = sentinel)

    // full lookback: sum all previous block totals in parallel
    int p = 0;
    if (tid < bx) {
        int w;
        do { w = atomicAdd(&g_flag[arr * NB + tid], 0); } while (w == 0);
        p = w - 1;
    }
#pragma unroll
    for (int o = 16; o; o >>= 1) p += __shfl_down_sync(0xffffffffu, p, o);
    if ((tid & 31) == 0) sred[tid >> 5] = p;
    __syncthreads();
    if (tid == 0) {
        int s = 0;
#pragma unroll
        for (int k = 0; k < 32; k++) s += sred[k];
        sprev_sh = s;
    }
    __syncthreads();
    int base = sprev_sh;

    if (i < NN) {
        int ex = base + sh[tid] - v;
        rowp[i] = ex;
        cur[i] = ex;
    }
    if (tid == 1023 && bx == NB - 1) rowp[NN] = base + total;

    // lp0 + x rows (H = 0 at step 0)
    if (arr == 0 && i < NN) {
        float lc = -g_selfsum[i];
#pragma unroll
        for (int k = 0; k < 16; k++) {
            float v0 = fmaxf(__ldg(&lpb1[2 * k])     + __ldg(&lpW1[(2 * k) * 65 + 64]) * lc, 0.f);
            float v1 = fmaxf(__ldg(&lpb1[2 * k + 1]) + __ldg(&lpW1[(2 * k + 1) * 65 + 64]) * lc, 0.f);
            g_S[(48 + k) * NN + i] = pk(v0, v1);
        }
        float x0 = __ldg(&x[i * 3]), x1 = __ldg(&x[i * 3 + 1]), x2 = __ldg(&x[i * 3 + 2]);
        g_S[64 * NN + i] = pk(x0, x1);
        g_S[65 * NN + i] = pk(x2, 0.f);
    }

    // device-wide sync (196 blocks, all resident)
    __syncthreads();
    if (tid == 0) {
        __threadfence();
        atomicAdd(&g_done, 1);
        while (atomicAdd(&g_done, 0) < 2 * NB) { }
    }
    __syncthreads();

    // scatter phase: grid-stride over all edges
    int gtid = (arr * NB + bx) * 1024 + tid;
    for (int e = gtid; e < EE; e += 2 * NB * 1024) {
        int s = ei[e];
        int d = ei[EE + e];
        if (s == d) continue;
        __half2 eh = __floats2half2_rn(ea[2 * e], ea[2 * e + 1]);
        unsigned ehu = *(unsigned*)&eh;
        u64 hi = ((u64)ehu) << 32;
        int p1 = atomicAdd(&g_cur_to[d], 1);
        g_pay_to[p1] = hi | (unsigned)s;
        int p2 = atomicAdd(&g_cur_fr[s], 1);
        g_pay_fr[p2] = hi | (unsigned)d;
    }
}

// ---------------- edge pass: 8 lanes/node, half2 math, fp32 flush every 2 edges ----------------
__global__ __launch_bounds__(256) void k_pass() {
    int gid = (blockIdx.x * 256 + threadIdx.x) >> 3;
    int k = threadIdx.x & 7;
    int dir = gid >= NN;
    int n = gid - dir * NN;
    if (n >= NN) return;

    const int*    rowp = dir ? g_rowp_fr : g_rowp_to;
    const u64*    pay  = dir ? g_pay_fr  : g_pay_to;
    const __half* stat = dir ? g_PsfH    : g_PdtH;
    const __half* gat  = dir ? g_PdfH    : g_PstH;

    __half2 wa0_01, wa0_23, wa1_01, wa1_23, b01, b23;
    upk2h(__ldg(&g_ewh[dir * 24 + k]),      wa0_01, wa0_23);
    upk2h(__ldg(&g_ewh[dir * 24 + 8 + k]),  wa1_01, wa1_23);
    upk2h(__ldg(&g_ewh[dir * 24 + 16 + k]), b01, b23);

    int beg = __ldg(&rowp[n]);
    int end = __ldg(&rowp[n + 1]);
    __half2 s01, s23;
    upk2h(__ldg((const u64*)&stat[n * 32 + 4 * k]), s01, s23);
    __half2 base01 = __hadd2(s01, b01);
    __half2 base23 = __hadd2(s23, b23);
    const __half2 hz2 = __floats2half2_rn(0.f, 0.f);
    __half2 ha01 = hz2, ha23 = hz2;
    float f0 = 0.f, f1 = 0.f, f2 = 0.f, f3 = 0.f;

#define EDGE_H(idxv, eah2) { \
    __half2 eax = __low2half2(eah2), eay = __high2half2(eah2); \
    __half2 g01, g23; \
    upk2h(__ldg((const u64*)&gat[(idxv) * 32 + 4 * k]), g01, g23); \
    __half2 z01 = __hfma2(eax, wa0_01, __hfma2(eay, wa1_01, __hadd2(base01, g01))); \
    __half2 z23 = __hfma2(eax, wa0_23, __hfma2(eay, wa1_23, __hadd2(base23, g23))); \
    ha01 = __hadd2(ha01, __hmax2(z01, hz2)); \
    ha23 = __hadd2(ha23, __hmax2(z23, hz2)); }

#define FLUSH_H { \
    float2 t_; \
    t_ = __half22float2(ha01); f0 += t_.x; f1 += t_.y; \
    t_ = __half22float2(ha23); f2 += t_.x; f3 += t_.y; \
    ha01 = hz2; ha23 = hz2; }

    int e = beg;
    if ((e & 1) && e < end) {           // peel to 16B alignment
        u64 p = __ldg(&pay[e]);
        unsigned ehu = (unsigned)(p >> 32);
        __half2 eap = *(__half2*)&ehu;
        EDGE_H((int)(unsigned)p, eap);
        FLUSH_H;
        e++;
    }
    for (; e + 1 < end; e += 2) {       // 2 payloads per LDG.128, flush each iter
        uint4 p2 = __ldg((const uint4*)&pay[e]);
        __half2 eaA = *(__half2*)&p2.y;
        __half2 eaB = *(__half2*)&p2.w;
        EDGE_H((int)p2.x, eaA);
        EDGE_H((int)p2.z, eaB);
        FLUSH_H;
    }
    if (e < end) {
        u64 p = __ldg(&pay[e]);
        unsigned ehu = (unsigned)(p >> 32);
        __half2 eap = *(__half2*)&ehu;
        EDGE_H((int)(unsigned)p, eap);
        FLUSH_H;
    }
    int cnt = end - beg;
    float rt = cnt > 0 ? 1.f / (float)cnt : 0.f;
    int rowb = 16 + dir * 16 + 2 * k;
    g_S[rowb * NN + n]       = pk(f0 * rt, f1 * rt);
    g_S[(rowb + 1) * NN + n] = pk(f2 * rt, f3 * rt);
#undef EDGE_H
#undef FLUSH_H
}

// ---------------- k_gru: output-stationary GEMV, coalesced row stream ----------------
__device__ __forceinline__ void consume(u64* acc, const u64* sGp, int j2, u64 c) {
    float v0, v1; upk(c, v0, v1);
    u64 s0 = pk(v0, v0), s1 = pk(v1, v1);
    const u64* w0p = &sGp[(2 * j2) * 48];
    const u64* w1p = w0p + 48;
#pragma unroll
    for (int qb = 0; qb < 24; qb++) {
        ulonglong2 w = *(const ulonglong2*)&w0p[qb * 2];
        ffma2(acc[qb * 2], w.x, s0);
        ffma2(acc[qb * 2 + 1], w.y, s0);
    }
#pragma unroll
    for (int qb = 0; qb < 24; qb++) {
        ulonglong2 w = *(const ulonglong2*)&w1p[qb * 2];
        ffma2(acc[qb * 2], w.x, s1);
        ffma2(acc[qb * 2 + 1], w.y, s1);
    }
}

__global__ __launch_bounds__(128, 3) void k_gru(const float* __restrict__ bhh) {
    extern __shared__ u64 smu[];
    u64*   sGp  = smu;                       // 6336 u64
    float* sb   = (float*)(smu + 6336);      // 96
    float* sct  = sb + 96;                   // 96
    float* scf  = sct + 96;                  // 96
    float* sbhn = scf + 96;                  // 32

    for (int i = threadIdx.x; i < 6336; i += 128) sGp[i] = g_Gp[i];
    for (int i = threadIdx.x; i < 96; i += 128) {
        sb[i] = g_bias[i]; sct[i] = g_cto[i]; scf[i] = g_cfr[i];
    }
    if (threadIdx.x < 32) sbhn[threadIdx.x] = bhh[64 + threadIdx.x];
    __syncthreads();

    int n = blockIdx.x * 128 + threadIdx.x;
    if (n >= NN) return;

    float ft = (__ldg(&g_cnt_to[n]) > 0) ? 1.f : 0.f;
    float ff = (__ldg(&g_cnt_fr[n]) > 0) ? 1.f : 0.f;

    u64 acc[48];
#pragma unroll
    for (int qp = 0; qp < 48; qp++) {
        int q0 = 2 * qp, q1 = q0 + 1;
        acc[qp] = pk(sb[q0] + ft * sct[q0] + ff * scf[q0],
                     sb[q1] + ft * sct[q1] + ff * scf[q1]);
    }

    // stream 66 coalesced u64 rows, branch-free prefetch depth 2 (rows 66/67 zero pad)
    u64 c0 = __ldg(&g_S[n]);
    u64 c1 = __ldg(&g_S[NN + n]);
    for (int j2 = 0; j2 < 66; j2++) {
        u64 cur = c0;
        c0 = c1;
        c1 = __ldg(&g_S[(j2 + 2) * NN + n]);
        consume(acc, sGp, j2, cur);
    }

#pragma unroll
    for (int i = 0; i < 16; i++) {
        float aR0, aR1, aZ0, aZ1, aN0, aN1;
        upk(acc[i], aR0, aR1);
        upk(acc[16 + i], aZ0, aZ1);
        upk(acc[32 + i], aN0, aN1);
        int q0 = 2 * i, q1 = q0 + 1;
        float r0 = 1.f / (1.f + __expf(-aR0));
        float r1 = 1.f / (1.f + __expf(-aR1));
        float z0 = 1.f / (1.f + __expf(-aZ0));
        float z1 = 1.f / (1.f + __expf(-aZ1));
        float tn0 = aN0 + r0 * sbhn[q0];
        float tn1 = aN1 + r1 * sbhn[q1];
        float th0 = 2.f / (1.f + __expf(-2.f * tn0)) - 1.f;
        float th1 = 2.f / (1.f + __expf(-2.f * tn1)) - 1.f;
        float h0, h1; upk(g_S[i * NN + n], h0, h1);
        h0 += 0.5f * (1.f - z0) * th0;   // ALPHA = 0.5
        h1 += 0.5f * (1.f - z1) * th1;
        g_S[i * NN + n] = pk(h0, h1);
    }
}

// ---------------- k_post: 4 parallel slices ----------------
// y=0: decode+loss   y=1: proj Pdt/Pdf   y=2: proj Pst/Psf   y=3: lp->rows 48-63
__global__ __launch_bounds__(128) void k_post(
        const float* __restrict__ toW1, const float* __restrict__ frW1,
        const float* __restrict__ lpW1, const float* __restrict__ lpb1,
        const float* __restrict__ dec1, const float* __restrict__ decb1,
        const float* __restrict__ dec2, const float* __restrict__ decb2,
        const float* __restrict__ y, float* __restrict__ outF, int loss_idx) {
    __shared__ float sW[2048];
    __shared__ float sD2[64];
    __shared__ float sDb1[32];
    __shared__ float sDb2[2];

    int slice = blockIdx.y;
    if (slice == 0) {
        for (int i = threadIdx.x; i < 1024; i += 128) sW[i] = dec1[i];
        if (threadIdx.x < 64) sD2[threadIdx.x] = dec2[threadIdx.x];
        if (threadIdx.x < 32) sDb1[threadIdx.x] = decb1[threadIdx.x];
        if (threadIdx.x < 2)  sDb2[threadIdx.x] = decb2[threadIdx.x];
    } else if (slice <= 2) {
        int half = slice - 1;
        for (int i = threadIdx.x; i < 2048; i += 128) {
            int m = half * 2 + (i >> 10), r = i & 1023, ii = r >> 5, j = r & 31;
            float v;
            if (m == 0)      v = toW1[ii * 66 + j];        // Pdt
            else if (m == 1) v = frW1[ii * 66 + 32 + j];   // Pdf
            else if (m == 2) v = toW1[ii * 66 + 32 + j];   // Pst
            else             v = frW1[ii * 66 + j];        // Psf
            sW[i] = v;
        }
    } else {
        for (int i = threadIdx.x; i < 1152; i += 128) {
            int tq = i / 36, c = i - tq * 36;
            float v = 0.f;
            if (c < 32)       v = lpW1[tq * 65 + c] + lpW1[tq * 65 + 32 + c];
            else if (c == 32) v = lpW1[tq * 65 + 64];
            sW[i] = v;
        }
        if (threadIdx.x < 32) sDb1[threadIdx.x] = lpb1[threadIdx.x];
    }
    __syncthreads();

    int n = blockIdx.x * 128 + threadIdx.x;
    if (n >= NN) return;

    u64 vHp[16];
#pragma unroll
    for (int k = 0; k < 16; k++) vHp[k] = __ldg(&g_S[k * NN + n]);

    if (slice == 0) {
        float F0 = sDb2[0], F1 = sDb2[1];
        for (int i = 0; i < 32; i++) {
            u64 acc = pk(sDb1[i], 0.f);
#pragma unroll
            for (int j4 = 0; j4 < 8; j4++) {
                ulonglong2 w = *(const ulonglong2*)&sW[i * 32 + j4 * 4];
                ffma2(acc, w.x, vHp[j4 * 2]);
                ffma2(acc, w.y, vHp[j4 * 2 + 1]);
            }
            float lo, hi; upk(acc, lo, hi);
            float a = fmaxf(lo + hi, 0.f);
            F0 += sD2[i] * a;
            F1 += sD2[32 + i] * a;
        }
        float d0 = F0 - y[n * 2], d1 = F1 - y[n * 2 + 1];
        float sse = d0 * d0 + d1 * d1;
        if (outF) { outF[n * 2] = F0; outF[n * 2 + 1] = F1; }
#pragma unroll
        for (int o = 16; o; o >>= 1) sse += __shfl_down_sync(0xffffffffu, sse, o);
        if ((threadIdx.x & 31) == 0) atomicAdd(&g_loss[loss_idx], sse);
    } else if (slice <= 2) {
        int half = slice - 1;
        __half* outA = half ? g_PstH : g_PdtH;
        __half* outB = half ? g_PsfH : g_PdfH;
        for (int i4 = 0; i4 < 8; i4++) {
            u64 A[8];
#pragma unroll
            for (int t = 0; t < 8; t++) A[t] = 0ull;
#pragma unroll
            for (int j4 = 0; j4 < 8; j4++) {
                u64 vlo = vHp[j4 * 2], vhi = vHp[j4 * 2 + 1];
#pragma unroll
                for (int mm = 0; mm < 2; mm++) {
#pragma unroll
                    for (int ii = 0; ii < 4; ii++) {
                        ulonglong2 w = *(const ulonglong2*)&sW[mm * 1024 + (i4 * 4 + ii) * 32 + j4 * 4];
                        ffma2(A[mm * 4 + ii], w.x, vlo);
                        ffma2(A[mm * 4 + ii], w.y, vhi);
                    }
                }
            }
            __half2 hA01, hA23, hB01, hB23;
            float l0, h0, l1, h1, l2, h2, l3, h3;
            upk(A[0], l0, h0); upk(A[1], l1, h1); upk(A[2], l2, h2); upk(A[3], l3, h3);
            hA01 = __floats2half2_rn(l0 + h0, l1 + h1);
            hA23 = __floats2half2_rn(l2 + h2, l3 + h3);
            upk(A[4], l0, h0); upk(A[5], l1, h1); upk(A[6], l2, h2); upk(A[7], l3, h3);
            hB01 = __floats2half2_rn(l0 + h0, l1 + h1);
            hB23 = __floats2half2_rn(l2 + h2, l3 + h3);
            uint2 stA, stB;
            stA.x = *(unsigned*)&hA01; stA.y = *(unsigned*)&hA23;
            stB.x = *(unsigned*)&hB01; stB.y = *(unsigned*)&hB23;
            *(uint2*)&outA[n * 32 + i4 * 4] = stA;
            *(uint2*)&outB[n * 32 + i4 * 4] = stB;
        }
    } else {
        float lc = -g_selfsum[n];
#pragma unroll
        for (int i2 = 0; i2 < 16; i2++) {
            int i0 = 2 * i2;
            u64 acc0 = pk(sDb1[i0]     + sW[i0 * 36 + 32] * lc, 0.f);
            u64 acc1 = pk(sDb1[i0 + 1] + sW[(i0 + 1) * 36 + 32] * lc, 0.f);
#pragma unroll
            for (int j4 = 0; j4 < 8; j4++) {
                ulonglong2 w0 = *(const ulonglong2*)&sW[i0 * 36 + j4 * 4];
                ulonglong2 w1 = *(const ulonglong2*)&sW[(i0 + 1) * 36 + j4 * 4];
                ffma2(acc0, w0.x, vHp[j4 * 2]); ffma2(acc0, w0.y, vHp[j4 * 2 + 1]);
                ffma2(acc1, w1.x, vHp[j4 * 2]); ffma2(acc1, w1.y, vHp[j4 * 2 + 1]);
            }
            float a0, b0, a1, b1;
            upk(acc0, a0, b0); upk(acc1, a1, b1);
            g_S[(48 + i2) * NN + n] = pk(fmaxf(a0 + b0, 0.f), fmaxf(a1 + b1, 0.f));
        }
    }
}

// ---------------- finalize losses + restore all inter-replay state ----------------
__global__ void k_final(float* __restrict__ out) {
    int t = blockIdx.x * blockDim.x + threadIdx.x;
    int nt = gridDim.x * blockDim.x;
    if (blockIdx.x == 0 && threadIdx.x == 0) {
        float inv = 1.f / (2.f * (float)NN);
        float l0 = g_loss[0] * inv;
        float l1 = g_loss[1] * inv;
        float l2 = g_loss[2] * inv;
        float l3 = g_loss[3] * inv;
        out[200000] = 0.729f * l0 + 0.81f * l1 + 0.9f * l2 + l3;
        out[200001] = l0; out[200002] = l1; out[200003] = l2; out[200004] = l3;
        g_loss[0] = 0.f; g_loss[1] = 0.f; g_loss[2] = 0.f; g_loss[3] = 0.f;
        g_done = 0;
    }
    __half hz = __float2half(0.f);
    for (int i = t; i < 16 * NN; i += nt) g_S[i] = 0ull;   // H rows
    for (int i = t; i < 32 * NN; i += nt) {
        g_PdtH[i] = hz; g_PdfH[i] = hz; g_PstH[i] = hz; g_PsfH[i] = hz;
    }
    for (int i = t; i < NN; i += nt) {
        g_cnt_to[i] = 0; g_cnt_fr[i] = 0; g_selfsum[i] = 0.f;
    }
    for (int i = t; i < 2 * NB; i += nt) g_flag[i] = 0;
}

// ---------------- launch ----------------
extern "C" void kernel_launch(void* const* d_in, const int* in_sizes, int n_in,
                              void* d_out, int out_size) {
    const float* x    = (const float*)d_in[0];
    const float* y    = (const float*)d_in[1];
    const int*   ei   = (const int*)d_in[2];
    const float* ea   = (const float*)d_in[3];
    const float* toW1 = (const float*)d_in[4];
    const float* tob1 = (const float*)d_in[5];
    const float* toW2 = (const float*)d_in[6];
    const float* tob2 = (const float*)d_in[7];
    const float* frW1 = (const float*)d_in[8];
    const float* frb1 = (const float*)d_in[9];
    const float* frW2 = (const float*)d_in[10];
    const float* frb2 = (const float*)d_in[11];
    const float* lpW1 = (const float*)d_in[12];
    const float* lpb1 = (const float*)d_in[13];
    const float* lpW2 = (const float*)d_in[14];
    const float* lpb2 = (const float*)d_in[15];
    const float* Wih  = (const float*)d_in[16];
    const float* bih  = (const float*)d_in[17];
    // d_in[18] = gru_Whh (unused: h0 = 0)
    const float* bhh  = (const float*)d_in[19];
    const float* dec1 = (const float*)d_in[20];
    const float* decb1= (const float*)d_in[21];
    const float* dec2 = (const float*)d_in[22];
    const float* decb2= (const float*)d_in[23];
    float* out = (float*)d_out;

    const int gru_smem = 6336 * 8 + 320 * 4;   // 51968 bytes
    cudaFuncSetAttribute(k_gru, cudaFuncAttributeMaxDynamicSharedMemorySize, gru_smem);

    k_cp<<<(EE + 255) / 256, 256>>>(ei, ea, Wih, bih, bhh,          // launch 0
                                    toW2, tob2, frW2, frb2, lpW2, lpb2,
                                    toW1, tob1, frW1, frb1);
    k_scansc<<<dim3(NB, 2), 1024>>>(ei, ea, lpW1, lpb1, x);         // launch 1

    int nblk = (NN + 127) / 128;
    for (int step = 0; step < 4; step++) {
        int do_proj = (step < 3) ? 1 : 0;
        k_pass<<<6250, 256>>>();                                    // step0 -> launch 2
        k_gru<<<nblk, 128, gru_smem>>>(bhh);                        // step0 -> launch 3 (profiled)
        dim3 pgrid(nblk, do_proj ? 4 : 1);
        k_post<<<pgrid, 128>>>(toW1, frW1, lpW1, lpb1, dec1, decb1, dec2, decb2, y,
                               (step == 3) ? out : nullptr, step);
    }
    k_final<<<1024, 256>>>(out);
}

// round 16
// speedup vs baseline: 1.5373x; 1.3597x over previous
#include <cuda_runtime.h>
#include <cuda_fp16.h>
#include <math.h>

#define NN 100000
#define EE 3200000
#define NB 98   // ceil(NN/1024)

typedef unsigned long long u64;

__device__ __forceinline__ u64 pk(float a, float b) {
    u64 r; asm("mov.b64 %0,{%1,%2};" : "=l"(r) : "f"(a), "f"(b)); return r;
}
__device__ __forceinline__ void upk(u64 v, float& a, float& b) {
    asm("mov.b64 {%0,%1},%2;" : "=f"(a), "=f"(b) : "l"(v));
}
__device__ __forceinline__ void ffma2(u64& d, u64 a, u64 b) {
    asm("fma.rn.f32x2 %0,%1,%2,%0;" : "+l"(d) : "l"(a), "l"(b));
}
__device__ __forceinline__ void upk2h(u64 v, __half2& a, __half2& b) {
    unsigned lo, hi;
    asm("mov.b64 {%0,%1},%2;" : "=r"(lo), "=r"(hi) : "l"(v));
    a = *(__half2*)&lo; b = *(__half2*)&hi;
}
__device__ __forceinline__ void mma16816(float* c, const unsigned* a, unsigned b0, unsigned b1) {
    asm volatile(
        "mma.sync.aligned.m16n8k16.row.col.f32.f16.f16.f32 "
        "{%0,%1,%2,%3}, {%4,%5,%6,%7}, {%8,%9}, {%0,%1,%2,%3};"
        : "+f"(c[0]), "+f"(c[1]), "+f"(c[2]), "+f"(c[3])
        : "r"(a[0]), "r"(a[1]), "r"(a[2]), "r"(a[3]), "r"(b0), "r"(b1));
}

// ---------------- device scratch ----------------
__device__ __align__(16) u64    g_S[16 * NN];       // fp32 H master, paired [k][n]
__device__ __align__(16) __half g_Bh[NN * 128];     // fp16 GEMM B: [n][k] k: H|m_to|m_fr|lp
__device__ __align__(16) __half g_PdtH[NN * 32];
__device__ __align__(16) __half g_PdfH[NN * 32];
__device__ __align__(16) __half g_PstH[NN * 32];
__device__ __align__(16) __half g_PsfH[NN * 32];
__device__ int   g_cnt_to[NN];
__device__ int   g_cnt_fr[NN];
__device__ float g_selfsum[NN];
__device__ float g_loss[4];

// CSR
__device__ int g_rowp_to[NN + 1];
__device__ int g_rowp_fr[NN + 1];
__device__ int g_cur_to[NN];
__device__ int g_cur_fr[NN];
__device__ __align__(16) u64 g_pay_to[EE];
__device__ __align__(16) u64 g_pay_fr[EE];
__device__ int g_flag[2 * NB];   // 0 = unpublished; else block_total + 1
__device__ int g_done;

// packed/folded weights
__device__ __align__(16) __half g_Gh[96 * 128];     // fp16 folded GRU weights [q][k]
__device__ __align__(16) float g_wx[96 * 3];        // x-block weights
__device__ float g_bias[96];
__device__ float g_cto[96];
__device__ float g_cfr[96];
__device__ __align__(16) u64 g_ewh[48];             // half2x2 edge weights

// ---------------- count + weight folding ----------------
__device__ __forceinline__ float gfold(int q, int c, const float* Wih,
                                       const float* toW2, const float* frW2,
                                       const float* lpW2) {
    if (c < 32) return Wih[q * 131 + c];
    if (c < 64) {
        float v = 0.f;
        for (int i = 0; i < 32; i++) v += Wih[q * 131 + 32 + i] * toW2[i * 32 + (c - 32)];
        return v;
    }
    if (c < 96) {
        float v = 0.f;
        for (int i = 0; i < 32; i++) v += Wih[q * 131 + 64 + i] * frW2[i * 32 + (c - 64)];
        return v;
    }
    float v = 0.f;
    for (int i = 0; i < 32; i++) v += Wih[q * 131 + 96 + i] * lpW2[i * 32 + (c - 96)];
    return v;
}

__global__ void k_cp(const int* __restrict__ ei, const float* __restrict__ ea,
                     const float* __restrict__ Wih, const float* __restrict__ bih,
                     const float* __restrict__ bhh,
                     const float* __restrict__ toW2, const float* __restrict__ tob2,
                     const float* __restrict__ frW2, const float* __restrict__ frb2,
                     const float* __restrict__ lpW2, const float* __restrict__ lpb2,
                     const float* __restrict__ toW1, const float* __restrict__ tob1,
                     const float* __restrict__ frW1, const float* __restrict__ frb1) {
    int t = blockIdx.x * blockDim.x + threadIdx.x;
    int nt = gridDim.x * blockDim.x;
    if (t < EE) {
        int s = ei[t];
        int d = ei[EE + t];
        if (s != d) {
            atomicAdd(&g_cnt_to[d], 1);
            atomicAdd(&g_cnt_fr[s], 1);
        } else {
            atomicAdd(&g_selfsum[s], ea[2 * t]);
        }
    }
    for (int idx = t; idx < 96 * 128; idx += nt) {
        int q = idx >> 7, k = idx & 127;
        g_Gh[idx] = __float2half(gfold(q, k, Wih, toW2, frW2, lpW2));
    }
    for (int i = t; i < 96 * 3; i += nt) {
        int q = i / 3, c = i - q * 3;
        g_wx[i] = Wih[q * 131 + 128 + c];
    }
    for (int q = t; q < 96; q += nt) {
        float b = bih[q], ct = 0.f, cf = 0.f;
        for (int i = 0; i < 32; i++) {
            b  += Wih[q * 131 + 96 + i] * lpb2[i];
            ct += Wih[q * 131 + 32 + i] * tob2[i];
            cf += Wih[q * 131 + 64 + i] * frb2[i];
        }
        if (q < 64) b += bhh[q];
        g_bias[q] = b; g_cto[q] = ct; g_cfr[q] = cf;
    }
    for (int i = t; i < 48; i += nt) {
        int dir = i / 24, r = (i % 24) / 8, k = i & 7;
        const float* W1 = dir ? frW1 : toW1;
        const float* b1 = dir ? frb1 : tob1;
        float v[4];
        for (int c = 0; c < 4; c++) {
            int j = 4 * k + c;
            v[c] = (r < 2) ? W1[j * 66 + 64 + r] : b1[j];
        }
        __half2 a = __floats2half2_rn(v[0], v[1]);
        __half2 b2 = __floats2half2_rn(v[2], v[3]);
        unsigned ua = *(unsigned*)&a, ub = *(unsigned*)&b2;
        g_ewh[i] = (((u64)ub) << 32) | ua;
    }
}

// ---------------- one-kernel CSR build + lp0 + B-H zero ----------------
__global__ __launch_bounds__(1024) void k_scansc(const int* __restrict__ ei,
                                                 const float* __restrict__ ea,
                                                 const float* __restrict__ lpW1,
                                                 const float* __restrict__ lpb1) {
    __shared__ int sh[1024];
    __shared__ int sred[32];
    __shared__ int sprev_sh;
    int arr = blockIdx.y, bx = blockIdx.x, tid = threadIdx.x;
    int i = bx * 1024 + tid;
    const int* cnt = arr ? g_cnt_fr : g_cnt_to;
    int* rowp = arr ? g_rowp_fr : g_rowp_to;
    int* cur  = arr ? g_cur_fr  : g_cur_to;

    int v = (i < NN) ? cnt[i] : 0;
    sh[tid] = v;
    __syncthreads();
#pragma unroll
    for (int off = 1; off < 1024; off <<= 1) {
        int t2 = (tid >= off) ? sh[tid - off] : 0;
        __syncthreads();
        sh[tid] += t2;
        __syncthreads();
    }
    int total = sh[1023];
    if (tid == 0) atomicExch(&g_flag[arr * NB + bx], total + 1);

    int p = 0;
    if (tid < bx) {
        int w;
        do { w = atomicAdd(&g_flag[arr * NB + tid], 0); } while (w == 0);
        p = w - 1;
    }
#pragma unroll
    for (int o = 16; o; o >>= 1) p += __shfl_down_sync(0xffffffffu, p, o);
    if ((tid & 31) == 0) sred[tid >> 5] = p;
    __syncthreads();
    if (tid == 0) {
        int s = 0;
#pragma unroll
        for (int k = 0; k < 32; k++) s += sred[k];
        sprev_sh = s;
    }
    __syncthreads();
    int base = sprev_sh;

    if (i < NN) {
        int ex = base + sh[tid] - v;
        rowp[i] = ex;
        cur[i] = ex;
    }
    if (tid == 1023 && bx == NB - 1) rowp[NN] = base + total;

    // lp0 (H=0) into g_Bh cols 96..127 fp16; zero H cols 0..31
    if (arr == 0 && i < NN) {
        float lc = -g_selfsum[i];
#pragma unroll
        for (int k = 0; k < 16; k++) {
            float v0 = fmaxf(__ldg(&lpb1[2 * k])     + __ldg(&lpW1[(2 * k) * 65 + 64]) * lc, 0.f);
            float v1 = fmaxf(__ldg(&lpb1[2 * k + 1]) + __ldg(&lpW1[(2 * k + 1) * 65 + 64]) * lc, 0.f);
            __half2 h = __floats2half2_rn(v0, v1);
            *(unsigned*)&g_Bh[(u64)i * 128 + 96 + 2 * k] = *(unsigned*)&h;
        }
        uint4 z4 = make_uint4(0, 0, 0, 0);
#pragma unroll
        for (int c = 0; c < 4; c++)
            *(uint4*)&g_Bh[(u64)i * 128 + 8 * c] = z4;
    }

    __syncthreads();
    if (tid == 0) {
        __threadfence();
        atomicAdd(&g_done, 1);
        while (atomicAdd(&g_done, 0) < 2 * NB) { }
    }
    __syncthreads();

    int gtid = (arr * NB + bx) * 1024 + tid;
    for (int e = gtid; e < EE; e += 2 * NB * 1024) {
        int s = ei[e];
        int d = ei[EE + e];
        if (s == d) continue;
        __half2 eh = __floats2half2_rn(ea[2 * e], ea[2 * e + 1]);
        unsigned ehu = *(unsigned*)&eh;
        u64 hi = ((u64)ehu) << 32;
        int p1 = atomicAdd(&g_cur_to[d], 1);
        g_pay_to[p1] = hi | (unsigned)s;
        int p2 = atomicAdd(&g_cur_fr[s], 1);
        g_pay_fr[p2] = hi | (unsigned)d;
    }
}

// ---------------- edge pass: 8 lanes/node, half2 math -> fp16 means into g_Bh ----------------
__global__ __launch_bounds__(256) void k_pass() {
    int gid = (blockIdx.x * 256 + threadIdx.x) >> 3;
    int k = threadIdx.x & 7;
    int dir = gid >= NN;
    int n = gid - dir * NN;
    if (n >= NN) return;

    const int*    rowp = dir ? g_rowp_fr : g_rowp_to;
    const u64*    pay  = dir ? g_pay_fr  : g_pay_to;
    const __half* stat = dir ? g_PsfH    : g_PdtH;
    const __half* gat  = dir ? g_PdfH    : g_PstH;

    __half2 wa0_01, wa0_23, wa1_01, wa1_23, b01, b23;
    upk2h(__ldg(&g_ewh[dir * 24 + k]),      wa0_01, wa0_23);
    upk2h(__ldg(&g_ewh[dir * 24 + 8 + k]),  wa1_01, wa1_23);
    upk2h(__ldg(&g_ewh[dir * 24 + 16 + k]), b01, b23);

    int beg = __ldg(&rowp[n]);
    int end = __ldg(&rowp[n + 1]);
    __half2 s01, s23;
    upk2h(__ldg((const u64*)&stat[n * 32 + 4 * k]), s01, s23);
    __half2 base01 = __hadd2(s01, b01);
    __half2 base23 = __hadd2(s23, b23);
    const __half2 hz2 = __floats2half2_rn(0.f, 0.f);
    __half2 ha01 = hz2, ha23 = hz2;
    float f0 = 0.f, f1 = 0.f, f2 = 0.f, f3 = 0.f;

#define EDGE_H(idxv, eah2) { \
    __half2 eax = __low2half2(eah2), eay = __high2half2(eah2); \
    __half2 g01, g23; \
    upk2h(__ldg((const u64*)&gat[(idxv) * 32 + 4 * k]), g01, g23); \
    __half2 z01 = __hfma2(eax, wa0_01, __hfma2(eay, wa1_01, __hadd2(base01, g01))); \
    __half2 z23 = __hfma2(eax, wa0_23, __hfma2(eay, wa1_23, __hadd2(base23, g23))); \
    ha01 = __hadd2(ha01, __hmax2(z01, hz2)); \
    ha23 = __hadd2(ha23, __hmax2(z23, hz2)); }

#define FLUSH_H { \
    float2 t_; \
    t_ = __half22float2(ha01); f0 += t_.x; f1 += t_.y; \
    t_ = __half22float2(ha23); f2 += t_.x; f3 += t_.y; \
    ha01 = hz2; ha23 = hz2; }

    int e = beg;
    if ((e & 1) && e < end) {
        u64 p = __ldg(&pay[e]);
        unsigned ehu = (unsigned)(p >> 32);
        __half2 eap = *(__half2*)&ehu;
        EDGE_H((int)(unsigned)p, eap);
        FLUSH_H;
        e++;
    }
    for (; e + 1 < end; e += 2) {
        uint4 p2 = __ldg((const uint4*)&pay[e]);
        __half2 eaA = *(__half2*)&p2.y;
        __half2 eaB = *(__half2*)&p2.w;
        EDGE_H((int)p2.x, eaA);
        EDGE_H((int)p2.z, eaB);
        FLUSH_H;
    }
    if (e < end) {
        u64 p = __ldg(&pay[e]);
        unsigned ehu = (unsigned)(p >> 32);
        __half2 eap = *(__half2*)&ehu;
        EDGE_H((int)(unsigned)p, eap);
        FLUSH_H;
    }
    int cnt = end - beg;
    float rt = cnt > 0 ? 1.f / (float)cnt : 0.f;
    __half2 o01 = __floats2half2_rn(f0 * rt, f1 * rt);
    __half2 o23 = __floats2half2_rn(f2 * rt, f3 * rt);
    unsigned u0 = *(unsigned*)&o01, u1 = *(unsigned*)&o23;
    *(u64*)&g_Bh[(u64)n * 128 + 32 + dir * 32 + 4 * k] = (((u64)u1) << 32) | u0;
#undef EDGE_H
#undef FLUSH_H
}

// ---------------- k_gmm: mma.sync fp16 GEMM (96x128 @ 128x128) + GRU epilogue ----------------
__global__ __launch_bounds__(256) void k_gmm(const float* __restrict__ bhh,
                                             const float* __restrict__ x) {
    extern __shared__ char smc[];
    float* sD    = (float*)smc;              // [96][128] f32 = 49152 B
    float* bias4 = (float*)(smc + 49152);    // 384
    float* sWx   = bias4 + 384;              // 288
    float* sbhn  = sWx + 288;                // 32
    int tid = threadIdx.x;
    int lane = tid & 31, wid = tid >> 5;
    int gid = lane >> 2, tig = lane & 3;

    for (int i = tid; i < 384; i += 256) {
        int v = i / 96, q = i - v * 96;
        bias4[i] = g_bias[q] + ((v & 1) ? g_cto[q] : 0.f) + ((v >> 1) ? g_cfr[q] : 0.f);
    }
    for (int i = tid; i < 288; i += 256) sWx[i] = g_wx[i];
    if (tid < 32) sbhn[tid] = bhh[64 + tid];

    int nbase = blockIdx.x * 128;
    float c[12][4];
#pragma unroll
    for (int t = 0; t < 12; t++) { c[t][0] = c[t][1] = c[t][2] = c[t][3] = 0.f; }

    int n0 = nbase + (wid * 2) * 8 + gid;     if (n0 >= NN) n0 = NN - 1;
    int n1 = nbase + (wid * 2 + 1) * 8 + gid; if (n1 >= NN) n1 = NN - 1;
    const __half* Brow0 = &g_Bh[(u64)n0 * 128 + 2 * tig];
    const __half* Brow1 = &g_Bh[(u64)n1 * 128 + 2 * tig];

#pragma unroll
    for (int ks = 0; ks < 8; ks++) {
        int k0 = ks * 16;
        unsigned a[6][4];
#pragma unroll
        for (int m = 0; m < 6; m++) {
            const __half* Ab = &g_Gh[(m * 16 + gid) * 128 + k0 + 2 * tig];
            a[m][0] = *(const unsigned*)Ab;
            a[m][1] = *(const unsigned*)(Ab + 8 * 128);
            a[m][2] = *(const unsigned*)(Ab + 8);
            a[m][3] = *(const unsigned*)(Ab + 8 * 128 + 8);
        }
        unsigned b00 = *(const unsigned*)(Brow0 + k0);
        unsigned b01 = *(const unsigned*)(Brow0 + k0 + 8);
        unsigned b10 = *(const unsigned*)(Brow1 + k0);
        unsigned b11 = *(const unsigned*)(Brow1 + k0 + 8);
#pragma unroll
        for (int m = 0; m < 6; m++) {
            mma16816(c[m * 2],     a[m], b00, b01);
            mma16816(c[m * 2 + 1], a[m], b10, b11);
        }
    }

    // D fragments -> SMEM planes
#pragma unroll
    for (int m = 0; m < 6; m++) {
#pragma unroll
        for (int t = 0; t < 2; t++) {
            int col = (wid * 2 + t) * 8 + 2 * tig;
            float* p0 = &sD[(m * 16 + gid) * 128 + col];
            float* p1 = &sD[(m * 16 + gid + 8) * 128 + col];
            p0[0] = c[m * 2 + t][0]; p0[1] = c[m * 2 + t][1];
            p1[0] = c[m * 2 + t][2]; p1[1] = c[m * 2 + t][3];
        }
    }
    __syncthreads();

    // epilogue: 2 threads per node, each handles 8 of the 16 H pairs
    int part = tid >> 7, nloc = tid & 127;
    int n = nbase + nloc;
    if (n < NN) {
        int vflag = ((__ldg(&g_cnt_to[n]) > 0) ? 1 : 0) | ((__ldg(&g_cnt_fr[n]) > 0) ? 2 : 0);
        const float* b4 = bias4 + vflag * 96;
        float x0 = __ldg(&x[n * 3]), x1 = __ldg(&x[n * 3 + 1]), x2 = __ldg(&x[n * 3 + 2]);
        int i2b = part * 8;
#pragma unroll
        for (int io = 0; io < 8; io++) {
            int i2 = i2b + io;
            float h0, h1; upk(g_S[i2 * NN + n], h0, h1);
            float nh[2];
#pragma unroll
            for (int sub = 0; sub < 2; sub++) {
                int i = 2 * i2 + sub;
                float aR = sD[i * 128 + nloc]        + b4[i]
                         + sWx[i * 3] * x0 + sWx[i * 3 + 1] * x1 + sWx[i * 3 + 2] * x2;
                float aZ = sD[(32 + i) * 128 + nloc] + b4[32 + i]
                         + sWx[(32 + i) * 3] * x0 + sWx[(32 + i) * 3 + 1] * x1 + sWx[(32 + i) * 3 + 2] * x2;
                float aN = sD[(64 + i) * 128 + nloc] + b4[64 + i]
                         + sWx[(64 + i) * 3] * x0 + sWx[(64 + i) * 3 + 1] * x1 + sWx[(64 + i) * 3 + 2] * x2;
                float r = 1.f / (1.f + __expf(-aR));
                float z = 1.f / (1.f + __expf(-aZ));
                float tn = aN + r * sbhn[i];
                float th = 2.f / (1.f + __expf(-2.f * tn)) - 1.f;
                nh[sub] = (sub ? h1 : h0) + 0.5f * (1.f - z) * th;   // ALPHA = 0.5
            }
            g_S[i2 * NN + n] = pk(nh[0], nh[1]);
            __half2 hh = __floats2half2_rn(nh[0], nh[1]);
            *(unsigned*)&g_Bh[(u64)n * 128 + 2 * i2] = *(unsigned*)&hh;
        }
    }
}

// ---------------- k_post: 4 parallel slices ----------------
// y=0: decode+loss   y=1: proj Pdt/Pdf   y=2: proj Pst/Psf   y=3: lp -> g_Bh cols 96..127
__global__ __launch_bounds__(128) void k_post(
        const float* __restrict__ toW1, const float* __restrict__ frW1,
        const float* __restrict__ lpW1, const float* __restrict__ lpb1,
        const float* __restrict__ dec1, const float* __restrict__ decb1,
        const float* __restrict__ dec2, const float* __restrict__ decb2,
        const float* __restrict__ y, float* __restrict__ outF, int loss_idx) {
    __shared__ float sW[2048];
    __shared__ float sD2[64];
    __shared__ float sDb1[32];
    __shared__ float sDb2[2];

    int slice = blockIdx.y;
    if (slice == 0) {
        for (int i = threadIdx.x; i < 1024; i += 128) sW[i] = dec1[i];
        if (threadIdx.x < 64) sD2[threadIdx.x] = dec2[threadIdx.x];
        if (threadIdx.x < 32) sDb1[threadIdx.x] = decb1[threadIdx.x];
        if (threadIdx.x < 2)  sDb2[threadIdx.x] = decb2[threadIdx.x];
    } else if (slice <= 2) {
        int half = slice - 1;
        for (int i = threadIdx.x; i < 2048; i += 128) {
            int m = half * 2 + (i >> 10), r = i & 1023, ii = r >> 5, j = r & 31;
            float v;
            if (m == 0)      v = toW1[ii * 66 + j];
            else if (m == 1) v = frW1[ii * 66 + 32 + j];
            else if (m == 2) v = toW1[ii * 66 + 32 + j];
            else             v = frW1[ii * 66 + j];
            sW[i] = v;
        }
    } else {
        for (int i = threadIdx.x; i < 1152; i += 128) {
            int tq = i / 36, c = i - tq * 36;
            float v = 0.f;
            if (c < 32)       v = lpW1[tq * 65 + c] + lpW1[tq * 65 + 32 + c];
            else if (c == 32) v = lpW1[tq * 65 + 64];
            sW[i] = v;
        }
        if (threadIdx.x < 32) sDb1[threadIdx.x] = lpb1[threadIdx.x];
    }
    __syncthreads();

    int n = blockIdx.x * 128 + threadIdx.x;
    if (n >= NN) return;

    u64 vHp[16];
#pragma unroll
    for (int k = 0; k < 16; k++) vHp[k] = __ldg(&g_S[k * NN + n]);

    if (slice == 0) {
        float F0 = sDb2[0], F1 = sDb2[1];
        for (int i = 0; i < 32; i++) {
            u64 acc = pk(sDb1[i], 0.f);
#pragma unroll
            for (int j4 = 0; j4 < 8; j4++) {
                ulonglong2 w = *(const ulonglong2*)&sW[i * 32 + j4 * 4];
                ffma2(acc, w.x, vHp[j4 * 2]);
                ffma2(acc, w.y, vHp[j4 * 2 + 1]);
            }
            float lo, hi; upk(acc, lo, hi);
            float a = fmaxf(lo + hi, 0.f);
            F0 += sD2[i] * a;
            F1 += sD2[32 + i] * a;
        }
        float d0 = F0 - y[n * 2], d1 = F1 - y[n * 2 + 1];
        float sse = d0 * d0 + d1 * d1;
        if (outF) { outF[n * 2] = F0; outF[n * 2 + 1] = F1; }
#pragma unroll
        for (int o = 16; o; o >>= 1) sse += __shfl_down_sync(0xffffffffu, sse, o);
        if ((threadIdx.x & 31) == 0) atomicAdd(&g_loss[loss_idx], sse);
    } else if (slice <= 2) {
        int half = slice - 1;
        __half* outA = half ? g_PstH : g_PdtH;
        __half* outB = half ? g_PsfH : g_PdfH;
        for (int i4 = 0; i4 < 8; i4++) {
            u64 A[8];
#pragma unroll
            for (int t = 0; t < 8; t++) A[t] = 0ull;
#pragma unroll
            for (int j4 = 0; j4 < 8; j4++) {
                u64 vlo = vHp[j4 * 2], vhi = vHp[j4 * 2 + 1];
#pragma unroll
                for (int mm = 0; mm < 2; mm++) {
#pragma unroll
                    for (int ii = 0; ii < 4; ii++) {
                        ulonglong2 w = *(const ulonglong2*)&sW[mm * 1024 + (i4 * 4 + ii) * 32 + j4 * 4];
                        ffma2(A[mm * 4 + ii], w.x, vlo);
                        ffma2(A[mm * 4 + ii], w.y, vhi);
                    }
                }
            }
            __half2 hA01, hA23, hB01, hB23;
            float l0, h0, l1, h1, l2, h2, l3, h3;
            upk(A[0], l0, h0); upk(A[1], l1, h1); upk(A[2], l2, h2); upk(A[3], l3, h3);
            hA01 = __floats2half2_rn(l0 + h0, l1 + h1);
            hA23 = __floats2half2_rn(l2 + h2, l3 + h3);
            upk(A[4], l0, h0); upk(A[5], l1, h1); upk(A[6], l2, h2); upk(A[7], l3, h3);
            hB01 = __floats2half2_rn(l0 + h0, l1 + h1);
            hB23 = __floats2half2_rn(l2 + h2, l3 + h3);
            uint2 stA, stB;
            stA.x = *(unsigned*)&hA01; stA.y = *(unsigned*)&hA23;
            stB.x = *(unsigned*)&hB01; stB.y = *(unsigned*)&hB23;
            *(uint2*)&outA[n * 32 + i4 * 4] = stA;
            *(uint2*)&outB[n * 32 + i4 * 4] = stB;
        }
    } else {
        float lc = -g_selfsum[n];
#pragma unroll
        for (int i2 = 0; i2 < 16; i2++) {
            int i0 = 2 * i2;
            u64 acc0 = pk(sDb1[i0]     + sW[i0 * 36 + 32] * lc, 0.f);
            u64 acc1 = pk(sDb1[i0 + 1] + sW[(i0 + 1) * 36 + 32] * lc, 0.f);
#pragma unroll
            for (int j4 = 0; j4 < 8; j4++) {
                ulonglong2 w0 = *(const ulonglong2*)&sW[i0 * 36 + j4 * 4];
                ulonglong2 w1 = *(const ulonglong2*)&sW[(i0 + 1) * 36 + j4 * 4];
                ffma2(acc0, w0.x, vHp[j4 * 2]); ffma2(acc0, w0.y, vHp[j4 * 2 + 1]);
                ffma2(acc1, w1.x, vHp[j4 * 2]); ffma2(acc1, w1.y, vHp[j4 * 2 + 1]);
            }
            float a0, b0, a1, b1;
            upk(acc0, a0, b0); upk(acc1, a1, b1);
            __half2 h = __floats2half2_rn(fmaxf(a0 + b0, 0.f), fmaxf(a1 + b1, 0.f));
            *(unsigned*)&g_Bh[(u64)n * 128 + 96 + 2 * i2] = *(unsigned*)&h;
        }
    }
}

// ---------------- finalize losses + restore inter-replay state ----------------
__global__ void k_final(float* __restrict__ out) {
    int t = blockIdx.x * blockDim.x + threadIdx.x;
    int nt = gridDim.x * blockDim.x;
    if (blockIdx.x == 0 && threadIdx.x == 0) {
        float inv = 1.f / (2.f * (float)NN);
        float l0 = g_loss[0] * inv;
        float l1 = g_loss[1] * inv;
        float l2 = g_loss[2] * inv;
        float l3 = g_loss[3] * inv;
        out[200000] = 0.729f * l0 + 0.81f * l1 + 0.9f * l2 + l3;
        out[200001] = l0; out[200002] = l1; out[200003] = l2; out[200004] = l3;
        g_loss[0] = 0.f; g_loss[1] = 0.f; g_loss[2] = 0.f; g_loss[3] = 0.f;
        g_done = 0;
    }
    __half hz = __float2half(0.f);
    for (int i = t; i < 16 * NN; i += nt) g_S[i] = 0ull;
    for (int i = t; i < 32 * NN; i += nt) {
        g_PdtH[i] = hz; g_PdfH[i] = hz; g_PstH[i] = hz; g_PsfH[i] = hz;
    }
    for (int i = t; i < NN; i += nt) {
        g_cnt_to[i] = 0; g_cnt_fr[i] = 0; g_selfsum[i] = 0.f;
    }
    for (int i = t; i < 2 * NB; i += nt) g_flag[i] = 0;
}

// ---------------- launch ----------------
extern "C" void kernel_launch(void* const* d_in, const int* in_sizes, int n_in,
                              void* d_out, int out_size) {
    const float* x    = (const float*)d_in[0];
    const float* y    = (const float*)d_in[1];
    const int*   ei   = (const int*)d_in[2];
    const float* ea   = (const float*)d_in[3];
    const float* toW1 = (const float*)d_in[4];
    const float* tob1 = (const float*)d_in[5];
    const float* toW2 = (const float*)d_in[6];
    const float* tob2 = (const float*)d_in[7];
    const float* frW1 = (const float*)d_in[8];
    const float* frb1 = (const float*)d_in[9];
    const float* frW2 = (const float*)d_in[10];
    const float* frb2 = (const float*)d_in[11];
    const float* lpW1 = (const float*)d_in[12];
    const float* lpb1 = (const float*)d_in[13];
    const float* lpW2 = (const float*)d_in[14];
    const float* lpb2 = (const float*)d_in[15];
    const float* Wih  = (const float*)d_in[16];
    const float* bih  = (const float*)d_in[17];
    // d_in[18] = gru_Whh (unused: h0 = 0)
    const float* bhh  = (const float*)d_in[19];
    const float* dec1 = (const float*)d_in[20];
    const float* decb1= (const float*)d_in[21];
    const float* dec2 = (const float*)d_in[22];
    const float* decb2= (const float*)d_in[23];
    float* out = (float*)d_out;

    const int gmm_smem = 49152 + (384 + 288 + 32) * 4;   // 51968 bytes
    cudaFuncSetAttribute(k_gmm, cudaFuncAttributeMaxDynamicSharedMemorySize, gmm_smem);

    k_cp<<<(EE + 255) / 256, 256>>>(ei, ea, Wih, bih, bhh,
                                    toW2, tob2, frW2, frb2, lpW2, lpb2,
                                    toW1, tob1, frW1, frb1);
    k_scansc<<<dim3(NB, 2), 1024>>>(ei, ea, lpW1, lpb1);

    int nblk = (NN + 127) / 128;
    for (int step = 0; step < 4; step++) {
        int do_proj = (step < 3) ? 1 : 0;
        k_pass<<<6250, 256>>>();
        k_gmm<<<nblk, 256, gmm_smem>>>(bhh, x);
        dim3 pgrid(nblk, do_proj ? 4 : 1);
        k_post<<<pgrid, 128>>>(toW1, frW1, lpW1, lpb1, dec1, decb1, dec2, decb2, y,
                               (step == 3) ? out : nullptr, step);
    }
    k_final<<<1024, 256>>>(out);
}

// round 17
// speedup vs baseline: 1.7667x; 1.1493x over previous
#include <cuda_runtime.h>
#include <cuda_fp16.h>
#include <math.h>

#define NN 100000
#define EE 3200000
#define NB 98   // ceil(NN/1024)
#define KK 144  // GEMM K: 128 data + x(3) + 1 + ft + ff + pad

typedef unsigned long long u64;

__device__ __forceinline__ u64 pk(float a, float b) {
    u64 r; asm("mov.b64 %0,{%1,%2};" : "=l"(r) : "f"(a), "f"(b)); return r;
}
__device__ __forceinline__ void upk(u64 v, float& a, float& b) {
    asm("mov.b64 {%0,%1},%2;" : "=f"(a), "=f"(b) : "l"(v));
}
__device__ __forceinline__ void ffma2(u64& d, u64 a, u64 b) {
    asm("fma.rn.f32x2 %0,%1,%2,%0;" : "+l"(d) : "l"(a), "l"(b));
}
__device__ __forceinline__ void upk2h(u64 v, __half2& a, __half2& b) {
    unsigned lo, hi;
    asm("mov.b64 {%0,%1},%2;" : "=r"(lo), "=r"(hi) : "l"(v));
    a = *(__half2*)&lo; b = *(__half2*)&hi;
}
__device__ __forceinline__ void mma16816(float* c, const unsigned* a, unsigned b0, unsigned b1) {
    asm volatile(
        "mma.sync.aligned.m16n8k16.row.col.f32.f16.f16.f32 "
        "{%0,%1,%2,%3}, {%4,%5,%6,%7}, {%8,%9}, {%0,%1,%2,%3};"
        : "+f"(c[0]), "+f"(c[1]), "+f"(c[2]), "+f"(c[3])
        : "r"(a[0]), "r"(a[1]), "r"(a[2]), "r"(a[3]), "r"(b0), "r"(b1));
}
__device__ __forceinline__ void ldm4(unsigned* r, unsigned saddr) {
    asm volatile("ldmatrix.sync.aligned.m8n8.x4.shared.b16 {%0,%1,%2,%3}, [%4];"
                 : "=r"(r[0]), "=r"(r[1]), "=r"(r[2]), "=r"(r[3]) : "r"(saddr));
}
__device__ __forceinline__ unsigned smem_u32(const void* p) {
    unsigned a;
    asm("{ .reg .u64 t; cvta.to.shared.u64 t, %1; cvt.u32.u64 %0, t; }" : "=r"(a) : "l"(p));
    return a;
}

// ---------------- device scratch ----------------
__device__ __align__(16) u64    g_S[16 * NN];       // fp32 H master, paired [k][n]
__device__ __align__(16) __half g_Bh[(u64)NN * KK]; // fp16 GEMM B rows
__device__ __align__(16) __half g_PdtH[NN * 32];
__device__ __align__(16) __half g_PdfH[NN * 32];
__device__ __align__(16) __half g_PstH[NN * 32];
__device__ __align__(16) __half g_PsfH[NN * 32];
__device__ int   g_cnt_to[NN];
__device__ int   g_cnt_fr[NN];
__device__ float g_selfsum[NN];
__device__ float g_loss[4];

// CSR
__device__ int g_rowp_to[NN + 1];
__device__ int g_rowp_fr[NN + 1];
__device__ int g_cur_to[NN];
__device__ int g_cur_fr[NN];
__device__ __align__(16) u64 g_pay_to[EE];
__device__ __align__(16) u64 g_pay_fr[EE];
__device__ int g_flag[2 * NB];   // 0 = unpublished; else block_total + 1
__device__ int g_done;

// packed/folded weights
__device__ __align__(16) __half g_Gh[96 * KK];      // fp16 folded GRU weights [q][k]
__device__ __align__(16) u64 g_ewh[48];             // half2x2 edge weights

// ---------------- count + weight folding ----------------
__device__ __forceinline__ float gfold(int q, int c, const float* Wih,
                                       const float* toW2, const float* frW2,
                                       const float* lpW2) {
    if (c < 32) return Wih[q * 131 + c];
    if (c < 64) {
        float v = 0.f;
        for (int i = 0; i < 32; i++) v += Wih[q * 131 + 32 + i] * toW2[i * 32 + (c - 32)];
        return v;
    }
    if (c < 96) {
        float v = 0.f;
        for (int i = 0; i < 32; i++) v += Wih[q * 131 + 64 + i] * frW2[i * 32 + (c - 64)];
        return v;
    }
    float v = 0.f;
    for (int i = 0; i < 32; i++) v += Wih[q * 131 + 96 + i] * lpW2[i * 32 + (c - 96)];
    return v;
}

__global__ void k_cp(const int* __restrict__ ei, const float* __restrict__ ea,
                     const float* __restrict__ Wih, const float* __restrict__ bih,
                     const float* __restrict__ bhh,
                     const float* __restrict__ toW2, const float* __restrict__ tob2,
                     const float* __restrict__ frW2, const float* __restrict__ frb2,
                     const float* __restrict__ lpW2, const float* __restrict__ lpb2,
                     const float* __restrict__ toW1, const float* __restrict__ tob1,
                     const float* __restrict__ frW1, const float* __restrict__ frb1) {
    int t = blockIdx.x * blockDim.x + threadIdx.x;
    int nt = gridDim.x * blockDim.x;
    if (t < EE) {
        int s = ei[t];
        int d = ei[EE + t];
        if (s != d) {
            atomicAdd(&g_cnt_to[d], 1);
            atomicAdd(&g_cnt_fr[s], 1);
        } else {
            atomicAdd(&g_selfsum[s], ea[2 * t]);
        }
    }
    // fp16 folded GEMM weights [q][k], K = 144 (H|m_to|m_fr|lp|x|1|ft|ff|pad)
    for (int idx = t; idx < 96 * KK; idx += nt) {
        int q = idx / KK, k = idx - q * KK;
        float v = 0.f;
        if (k < 128) {
            v = gfold(q, k, Wih, toW2, frW2, lpW2);
        } else if (k < 131) {
            v = Wih[q * 131 + 128 + (k - 128)];          // wx
        } else if (k == 131) {
            v = bih[q];
            for (int i = 0; i < 32; i++) v += Wih[q * 131 + 96 + i] * lpb2[i];
            if (q < 64) v += bhh[q];                     // b_hr / b_hz
        } else if (k == 132) {
            for (int i = 0; i < 32; i++) v += Wih[q * 131 + 32 + i] * tob2[i];
        } else if (k == 133) {
            for (int i = 0; i < 32; i++) v += Wih[q * 131 + 64 + i] * frb2[i];
        }
        g_Gh[idx] = __float2half(v);
    }
    for (int i = t; i < 48; i += nt) {
        int dir = i / 24, r = (i % 24) / 8, k = i & 7;
        const float* W1 = dir ? frW1 : toW1;
        const float* b1 = dir ? frb1 : tob1;
        float v[4];
        for (int c = 0; c < 4; c++) {
            int j = 4 * k + c;
            v[c] = (r < 2) ? W1[j * 66 + 64 + r] : b1[j];
        }
        __half2 a = __floats2half2_rn(v[0], v[1]);
        __half2 b2 = __floats2half2_rn(v[2], v[3]);
        unsigned ua = *(unsigned*)&a, ub = *(unsigned*)&b2;
        g_ewh[i] = (((u64)ub) << 32) | ua;
    }
}

// ---------------- one-kernel CSR build + lp0 + static B cols ----------------
__global__ __launch_bounds__(1024) void k_scansc(const int* __restrict__ ei,
                                                 const float* __restrict__ ea,
                                                 const float* __restrict__ lpW1,
                                                 const float* __restrict__ lpb1,
                                                 const float* __restrict__ x) {
    __shared__ int sh[1024];
    __shared__ int sred[32];
    __shared__ int sprev_sh;
    int arr = blockIdx.y, bx = blockIdx.x, tid = threadIdx.x;
    int i = bx * 1024 + tid;
    const int* cnt = arr ? g_cnt_fr : g_cnt_to;
    int* rowp = arr ? g_rowp_fr : g_rowp_to;
    int* cur  = arr ? g_cur_fr  : g_cur_to;

    int v = (i < NN) ? cnt[i] : 0;
    sh[tid] = v;
    __syncthreads();
#pragma unroll
    for (int off = 1; off < 1024; off <<= 1) {
        int t2 = (tid >= off) ? sh[tid - off] : 0;
        __syncthreads();
        sh[tid] += t2;
        __syncthreads();
    }
    int total = sh[1023];
    if (tid == 0) atomicExch(&g_flag[arr * NB + bx], total + 1);

    int p = 0;
    if (tid < bx) {
        int w;
        do { w = atomicAdd(&g_flag[arr * NB + tid], 0); } while (w == 0);
        p = w - 1;
    }
#pragma unroll
    for (int o = 16; o; o >>= 1) p += __shfl_down_sync(0xffffffffu, p, o);
    if ((tid & 31) == 0) sred[tid >> 5] = p;
    __syncthreads();
    if (tid == 0) {
        int s = 0;
#pragma unroll
        for (int k = 0; k < 32; k++) s += sred[k];
        sprev_sh = s;
    }
    __syncthreads();
    int base = sprev_sh;

    if (i < NN) {
        int ex = base + sh[tid] - v;
        rowp[i] = ex;
        cur[i] = ex;
    }
    if (tid == 1023 && bx == NB - 1) rowp[NN] = base + total;

    // lp0 (H=0) into cols 96..127; zero H cols; static cols 128..143
    if (arr == 0 && i < NN) {
        u64 rb = (u64)i * KK;
        float lc = -g_selfsum[i];
#pragma unroll
        for (int k = 0; k < 16; k++) {
            float v0 = fmaxf(__ldg(&lpb1[2 * k])     + __ldg(&lpW1[(2 * k) * 65 + 64]) * lc, 0.f);
            float v1 = fmaxf(__ldg(&lpb1[2 * k + 1]) + __ldg(&lpW1[(2 * k + 1) * 65 + 64]) * lc, 0.f);
            __half2 h = __floats2half2_rn(v0, v1);
            *(unsigned*)&g_Bh[rb + 96 + 2 * k] = *(unsigned*)&h;
        }
        uint4 z4 = make_uint4(0, 0, 0, 0);
#pragma unroll
        for (int c = 0; c < 4; c++)
            *(uint4*)&g_Bh[rb + 8 * c] = z4;
        float x0 = __ldg(&x[i * 3]), x1 = __ldg(&x[i * 3 + 1]), x2 = __ldg(&x[i * 3 + 2]);
        float ft = (v > 0) ? 1.f : 0.f;
        float ff = (__ldg(&g_cnt_fr[i]) > 0) ? 1.f : 0.f;
        __half2 h;
        h = __floats2half2_rn(x0, x1);  *(unsigned*)&g_Bh[rb + 128] = *(unsigned*)&h;
        h = __floats2half2_rn(x2, 1.f); *(unsigned*)&g_Bh[rb + 130] = *(unsigned*)&h;
        h = __floats2half2_rn(ft, ff);  *(unsigned*)&g_Bh[rb + 132] = *(unsigned*)&h;
        h = __floats2half2_rn(0.f, 0.f);
#pragma unroll
        for (int c = 0; c < 5; c++) *(unsigned*)&g_Bh[rb + 134 + 2 * c] = *(unsigned*)&h;
    }

    __syncthreads();
    if (tid == 0) {
        __threadfence();
        atomicAdd(&g_done, 1);
        while (atomicAdd(&g_done, 0) < 2 * NB) { }
    }
    __syncthreads();

    int gtid = (arr * NB + bx) * 1024 + tid;
    for (int e = gtid; e < EE; e += 2 * NB * 1024) {
        int s = ei[e];
        int d = ei[EE + e];
        if (s == d) continue;
        __half2 eh = __floats2half2_rn(ea[2 * e], ea[2 * e + 1]);
        unsigned ehu = *(unsigned*)&eh;
        u64 hi = ((u64)ehu) << 32;
        int p1 = atomicAdd(&g_cur_to[d], 1);
        g_pay_to[p1] = hi | (unsigned)s;
        int p2 = atomicAdd(&g_cur_fr[s], 1);
        g_pay_fr[p2] = hi | (unsigned)d;
    }
}

// ---------------- edge pass: 8 lanes/node, half2 math, flush every 4 edges ----------------
__global__ __launch_bounds__(256) void k_pass() {
    int gid = (blockIdx.x * 256 + threadIdx.x) >> 3;
    int k = threadIdx.x & 7;
    int dir = gid >= NN;
    int n = gid - dir * NN;
    if (n >= NN) return;

    const int*    rowp = dir ? g_rowp_fr : g_rowp_to;
    const u64*    pay  = dir ? g_pay_fr  : g_pay_to;
    const __half* stat = dir ? g_PsfH    : g_PdtH;
    const __half* gat  = dir ? g_PdfH    : g_PstH;

    __half2 wa0_01, wa0_23, wa1_01, wa1_23, b01, b23;
    upk2h(__ldg(&g_ewh[dir * 24 + k]),      wa0_01, wa0_23);
    upk2h(__ldg(&g_ewh[dir * 24 + 8 + k]),  wa1_01, wa1_23);
    upk2h(__ldg(&g_ewh[dir * 24 + 16 + k]), b01, b23);

    int beg = __ldg(&rowp[n]);
    int end = __ldg(&rowp[n + 1]);
    __half2 s01, s23;
    upk2h(__ldg((const u64*)&stat[n * 32 + 4 * k]), s01, s23);
    __half2 base01 = __hadd2(s01, b01);
    __half2 base23 = __hadd2(s23, b23);
    const __half2 hz2 = __floats2half2_rn(0.f, 0.f);
    __half2 ha01 = hz2, ha23 = hz2;
    float f0 = 0.f, f1 = 0.f, f2 = 0.f, f3 = 0.f;

#define EDGE_H(idxv, eah2) { \
    __half2 eax = __low2half2(eah2), eay = __high2half2(eah2); \
    __half2 g01, g23; \
    upk2h(__ldg((const u64*)&gat[(idxv) * 32 + 4 * k]), g01, g23); \
    __half2 z01 = __hfma2(eax, wa0_01, __hfma2(eay, wa1_01, __hadd2(base01, g01))); \
    __half2 z23 = __hfma2(eax, wa0_23, __hfma2(eay, wa1_23, __hadd2(base23, g23))); \
    ha01 = __hadd2(ha01, __hmax2(z01, hz2)); \
    ha23 = __hadd2(ha23, __hmax2(z23, hz2)); }

#define FLUSH_H { \
    float2 t_; \
    t_ = __half22float2(ha01); f0 += t_.x; f1 += t_.y; \
    t_ = __half22float2(ha23); f2 += t_.x; f3 += t_.y; \
    ha01 = hz2; ha23 = hz2; }

    int e = beg;
    if ((e & 1) && e < end) {           // peel to 16B alignment
        u64 p = __ldg(&pay[e]);
        unsigned ehu = (unsigned)(p >> 32);
        __half2 eap = *(__half2*)&ehu;
        EDGE_H((int)(unsigned)p, eap);
        FLUSH_H;
        e++;
    }
    for (; e + 3 < end; e += 4) {       // 4 edges per flush
        uint4 pa = __ldg((const uint4*)&pay[e]);
        uint4 pb = __ldg((const uint4*)&pay[e + 2]);
        __half2 eaA = *(__half2*)&pa.y;
        __half2 eaB = *(__half2*)&pa.w;
        __half2 eaC = *(__half2*)&pb.y;
        __half2 eaD = *(__half2*)&pb.w;
        EDGE_H((int)pa.x, eaA);
        EDGE_H((int)pa.z, eaB);
        EDGE_H((int)pb.x, eaC);
        EDGE_H((int)pb.z, eaD);
        FLUSH_H;
    }
    for (; e + 1 < end; e += 2) {
        uint4 p2 = __ldg((const uint4*)&pay[e]);
        __half2 eaA = *(__half2*)&p2.y;
        __half2 eaB = *(__half2*)&p2.w;
        EDGE_H((int)p2.x, eaA);
        EDGE_H((int)p2.z, eaB);
        FLUSH_H;
    }
    if (e < end) {
        u64 p = __ldg(&pay[e]);
        unsigned ehu = (unsigned)(p >> 32);
        __half2 eap = *(__half2*)&ehu;
        EDGE_H((int)(unsigned)p, eap);
        FLUSH_H;
    }
    int cnt = end - beg;
    float rt = cnt > 0 ? 1.f / (float)cnt : 0.f;
    __half2 o01 = __floats2half2_rn(f0 * rt, f1 * rt);
    __half2 o23 = __floats2half2_rn(f2 * rt, f3 * rt);
    unsigned u0 = *(unsigned*)&o01, u1 = *(unsigned*)&o23;
    *(u64*)&g_Bh[(u64)n * KK + 32 + dir * 32 + 4 * k] = (((u64)u1) << 32) | u0;
#undef EDGE_H
#undef FLUSH_H
}

// ---------------- k_gmm: ldmatrix + mma.sync, register GRU epilogue ----------------
#define ASTRIDE 152   // halves per A row in SMEM (pad for ldmatrix bank spread)
__global__ __launch_bounds__(256) void k_gmm(const float* __restrict__ bhh) {
    extern __shared__ char smc[];
    __half* sA     = (__half*)smc;                 // 96*152*2 = 29184 B (union w/ strans)
    float*  strans = (float*)smc;                  // 32*136*4 = 17408 B (after mainloop)
    float*  sbhn   = (float*)(smc + 29184);        // 32 floats
    int tid = threadIdx.x;
    int lane = tid & 31, wid = tid >> 5;
    int gid = lane >> 2, tig = lane & 3;

    if (tid < 32) sbhn[tid] = bhh[64 + tid];
    // stage A (96 x 144 fp16) into padded SMEM
    for (int idx = tid; idx < 96 * 18; idx += 256) {
        int row = idx / 18, seg = idx - row * 18;
        uint4 v = __ldg((const uint4*)&g_Gh[row * KK + seg * 8]);
        *(uint4*)&sA[row * ASTRIDE + seg * 8] = v;
    }
    __syncthreads();

    int nbase = blockIdx.x * 128;
    float c[12][4];
#pragma unroll
    for (int t = 0; t < 12; t++) { c[t][0] = c[t][1] = c[t][2] = c[t][3] = 0.f; }

    int n0 = nbase + wid * 16 + gid;     if (n0 >= NN) n0 = NN - 1;
    int n1 = n0 + 8;                      if (n1 >= NN) n1 = NN - 1;
    const __half* Brow0 = &g_Bh[(u64)n0 * KK + 2 * tig];
    const __half* Brow1 = &g_Bh[(u64)n1 * KK + 2 * tig];

    int ldm_row  = (lane & 7) + 8 * ((lane >> 3) & 1);
    int ldm_colg = (lane >> 4) * 8;
    unsigned sAu = smem_u32(sA);

#pragma unroll
    for (int ks = 0; ks < 9; ks++) {
        int k0 = ks * 16;
        unsigned b00 = *(const unsigned*)(Brow0 + k0);
        unsigned b01 = *(const unsigned*)(Brow0 + k0 + 8);
        unsigned b10 = *(const unsigned*)(Brow1 + k0);
        unsigned b11 = *(const unsigned*)(Brow1 + k0 + 8);
#pragma unroll
        for (int m = 0; m < 6; m++) {
            unsigned a[4];
            unsigned addr = sAu + (unsigned)(((m * 16 + ldm_row) * ASTRIDE + k0 + ldm_colg) * 2);
            ldm4(a, addr);
            mma16816(c[m * 2],     a, b00, b01);
            mma16816(c[m * 2 + 1], a, b10, b11);
        }
    }
    __syncthreads();   // A region now dead; reuse as strans

    // GRU nonlinearity in registers; write delta to transpose buffer
#pragma unroll
    for (int mi = 0; mi < 2; mi++) {
#pragma unroll
        for (int half = 0; half < 2; half++) {
            int q = mi * 16 + 8 * half + gid;
            float bn = sbhn[q];
#pragma unroll
            for (int t = 0; t < 2; t++) {
#pragma unroll
                for (int col = 0; col < 2; col++) {
                    int ri = half * 2 + col;
                    float aR = c[mi * 2 + t][ri];
                    float aZ = c[(2 + mi) * 2 + t][ri];
                    float aN = c[(4 + mi) * 2 + t][ri];
                    float r = 1.f / (1.f + __expf(-aR));
                    float z = 1.f / (1.f + __expf(-aZ));
                    float tn = aN + r * bn;
                    float th = 2.f / (1.f + __expf(-2.f * tn)) - 1.f;
                    int nc = wid * 16 + t * 8 + 2 * tig + col;
                    strans[q * 136 + nc] = 0.5f * (1.f - z) * th;   // ALPHA = 0.5
                }
            }
        }
    }
    __syncthreads();

    // writer phase: 128 threads, one node each — coalesced H update + Bh mirror
    if (tid < 128) {
        int n = nbase + tid;
        if (n < NN) {
            unsigned hout[16];
#pragma unroll
            for (int k = 0; k < 16; k++) {
                float h0, h1; upk(g_S[k * NN + n], h0, h1);
                h0 += strans[(2 * k) * 136 + tid];
                h1 += strans[(2 * k + 1) * 136 + tid];
                g_S[k * NN + n] = pk(h0, h1);
                __half2 hh = __floats2half2_rn(h0, h1);
                hout[k] = *(unsigned*)&hh;
            }
            uint4* dst = (uint4*)&g_Bh[(u64)n * KK];
#pragma unroll
            for (int cidx = 0; cidx < 4; cidx++)
                dst[cidx] = make_uint4(hout[cidx * 4], hout[cidx * 4 + 1],
                                       hout[cidx * 4 + 2], hout[cidx * 4 + 3]);
        }
    }
}

// ---------------- k_post: 4 parallel slices ----------------
__global__ __launch_bounds__(128) void k_post(
        const float* __restrict__ toW1, const float* __restrict__ frW1,
        const float* __restrict__ lpW1, const float* __restrict__ lpb1,
        const float* __restrict__ dec1, const float* __restrict__ decb1,
        const float* __restrict__ dec2, const float* __restrict__ decb2,
        const float* __restrict__ y, float* __restrict__ outF, int loss_idx) {
    __shared__ float sW[2048];
    __shared__ float sD2[64];
    __shared__ float sDb1[32];
    __shared__ float sDb2[2];

    int slice = blockIdx.y;
    if (slice == 0) {
        for (int i = threadIdx.x; i < 1024; i += 128) sW[i] = dec1[i];
        if (threadIdx.x < 64) sD2[threadIdx.x] = dec2[threadIdx.x];
        if (threadIdx.x < 32) sDb1[threadIdx.x] = decb1[threadIdx.x];
        if (threadIdx.x < 2)  sDb2[threadIdx.x] = decb2[threadIdx.x];
    } else if (slice <= 2) {
        int half = slice - 1;
        for (int i = threadIdx.x; i < 2048; i += 128) {
            int m = half * 2 + (i >> 10), r = i & 1023, ii = r >> 5, j = r & 31;
            float v;
            if (m == 0)      v = toW1[ii * 66 + j];
            else if (m == 1) v = frW1[ii * 66 + 32 + j];
            else if (m == 2) v = toW1[ii * 66 + 32 + j];
            else             v = frW1[ii * 66 + j];
            sW[i] = v;
        }
    } else {
        for (int i = threadIdx.x; i < 1152; i += 128) {
            int tq = i / 36, c = i - tq * 36;
            float v = 0.f;
            if (c < 32)       v = lpW1[tq * 65 + c] + lpW1[tq * 65 + 32 + c];
            else if (c == 32) v = lpW1[tq * 65 + 64];
            sW[i] = v;
        }
        if (threadIdx.x < 32) sDb1[threadIdx.x] = lpb1[threadIdx.x];
    }
    __syncthreads();

    int n = blockIdx.x * 128 + threadIdx.x;
    if (n >= NN) return;

    u64 vHp[16];
#pragma unroll
    for (int k = 0; k < 16; k++) vHp[k] = __ldg(&g_S[k * NN + n]);

    if (slice == 0) {
        float F0 = sDb2[0], F1 = sDb2[1];
        for (int i = 0; i < 32; i++) {
            u64 acc = pk(sDb1[i], 0.f);
#pragma unroll
            for (int j4 = 0; j4 < 8; j4++) {
                ulonglong2 w = *(const ulonglong2*)&sW[i * 32 + j4 * 4];
                ffma2(acc, w.x, vHp[j4 * 2]);
                ffma2(acc, w.y, vHp[j4 * 2 + 1]);
            }
            float lo, hi; upk(acc, lo, hi);
            float a = fmaxf(lo + hi, 0.f);
            F0 += sD2[i] * a;
            F1 += sD2[32 + i] * a;
        }
        float d0 = F0 - y[n * 2], d1 = F1 - y[n * 2 + 1];
        float sse = d0 * d0 + d1 * d1;
        if (outF) { outF[n * 2] = F0; outF[n * 2 + 1] = F1; }
#pragma unroll
        for (int o = 16; o; o >>= 1) sse += __shfl_down_sync(0xffffffffu, sse, o);
        if ((threadIdx.x & 31) == 0) atomicAdd(&g_loss[loss_idx], sse);
    } else if (slice <= 2) {
        int half = slice - 1;
        __half* outA = half ? g_PstH : g_PdtH;
        __half* outB = half ? g_PsfH : g_PdfH;
        for (int i4 = 0; i4 < 8; i4++) {
            u64 A[8];
#pragma unroll
            for (int t = 0; t < 8; t++) A[t] = 0ull;
#pragma unroll
            for (int j4 = 0; j4 < 8; j4++) {
                u64 vlo = vHp[j4 * 2], vhi = vHp[j4 * 2 + 1];
#pragma unroll
                for (int mm = 0; mm < 2; mm++) {
#pragma unroll
                    for (int ii = 0; ii < 4; ii++) {
                        ulonglong2 w = *(const ulonglong2*)&sW[mm * 1024 + (i4 * 4 + ii) * 32 + j4 * 4];
                        ffma2(A[mm * 4 + ii], w.x, vlo);
                        ffma2(A[mm * 4 + ii], w.y, vhi);
                    }
                }
            }
            __half2 hA01, hA23, hB01, hB23;
            float l0, h0, l1, h1, l2, h2, l3, h3;
            upk(A[0], l0, h0); upk(A[1], l1, h1); upk(A[2], l2, h2); upk(A[3], l3, h3);
            hA01 = __floats2half2_rn(l0 + h0, l1 + h1);
            hA23 = __floats2half2_rn(l2 + h2, l3 + h3);
            upk(A[4], l0, h0); upk(A[5], l1, h1); upk(A[6], l2, h2); upk(A[7], l3, h3);
            hB01 = __floats2half2_rn(l0 + h0, l1 + h1);
            hB23 = __floats2half2_rn(l2 + h2, l3 + h3);
            uint2 stA, stB;
            stA.x = *(unsigned*)&hA01; stA.y = *(unsigned*)&hA23;
            stB.x = *(unsigned*)&hB01; stB.y = *(unsigned*)&hB23;
            *(uint2*)&outA[n * 32 + i4 * 4] = stA;
            *(uint2*)&outB[n * 32 + i4 * 4] = stB;
        }
    } else {
        float lc = -g_selfsum[n];
#pragma unroll
        for (int i2 = 0; i2 < 16; i2++) {
            int i0 = 2 * i2;
            u64 acc0 = pk(sDb1[i0]     + sW[i0 * 36 + 32] * lc, 0.f);
            u64 acc1 = pk(sDb1[i0 + 1] + sW[(i0 + 1) * 36 + 32] * lc, 0.f);
#pragma unroll
            for (int j4 = 0; j4 < 8; j4++) {
                ulonglong2 w0 = *(const ulonglong2*)&sW[i0 * 36 + j4 * 4];
                ulonglong2 w1 = *(const ulonglong2*)&sW[(i0 + 1) * 36 + j4 * 4];
                ffma2(acc0, w0.x, vHp[j4 * 2]); ffma2(acc0, w0.y, vHp[j4 * 2 + 1]);
                ffma2(acc1, w1.x, vHp[j4 * 2]); ffma2(acc1, w1.y, vHp[j4 * 2 + 1]);
            }
            float a0, b0, a1, b1;
            upk(acc0, a0, b0); upk(acc1, a1, b1);
            __half2 h = __floats2half2_rn(fmaxf(a0 + b0, 0.f), fmaxf(a1 + b1, 0.f));
            *(unsigned*)&g_Bh[(u64)n * KK + 96 + 2 * i2] = *(unsigned*)&h;
        }
    }
}

// ---------------- finalize losses + restore inter-replay state ----------------
__global__ void k_final(float* __restrict__ out) {
    int t = blockIdx.x * blockDim.x + threadIdx.x;
    int nt = gridDim.x * blockDim.x;
    if (blockIdx.x == 0 && threadIdx.x == 0) {
        float inv = 1.f / (2.f * (float)NN);
        float l0 = g_loss[0] * inv;
        float l1 = g_loss[1] * inv;
        float l2 = g_loss[2] * inv;
        float l3 = g_loss[3] * inv;
        out[200000] = 0.729f * l0 + 0.81f * l1 + 0.9f * l2 + l3;
        out[200001] = l0; out[200002] = l1; out[200003] = l2; out[200004] = l3;
        g_loss[0] = 0.f; g_loss[1] = 0.f; g_loss[2] = 0.f; g_loss[3] = 0.f;
        g_done = 0;
    }
    __half hz = __float2half(0.f);
    for (int i = t; i < 16 * NN; i += nt) g_S[i] = 0ull;
    for (int i = t; i < 32 * NN; i += nt) {
        g_PdtH[i] = hz; g_PdfH[i] = hz; g_PstH[i] = hz; g_PsfH[i] = hz;
    }
    for (int i = t; i < NN; i += nt) {
        g_cnt_to[i] = 0; g_cnt_fr[i] = 0; g_selfsum[i] = 0.f;
    }
    for (int i = t; i < 2 * NB; i += nt) g_flag[i] = 0;
}

// ---------------- launch ----------------
extern "C" void kernel_launch(void* const* d_in, const int* in_sizes, int n_in,
                              void* d_out, int out_size) {
    const float* x    = (const float*)d_in[0];
    const float* y    = (const float*)d_in[1];
    const int*   ei   = (const int*)d_in[2];
    const float* ea   = (const float*)d_in[3];
    const float* toW1 = (const float*)d_in[4];
    const float* tob1 = (const float*)d_in[5];
    const float* toW2 = (const float*)d_in[6];
    const float* tob2 = (const float*)d_in[7];
    const float* frW1 = (const float*)d_in[8];
    const float* frb1 = (const float*)d_in[9];
    const float* frW2 = (const float*)d_in[10];
    const float* frb2 = (const float*)d_in[11];
    const float* lpW1 = (const float*)d_in[12];
    const float* lpb1 = (const float*)d_in[13];
    const float* lpW2 = (const float*)d_in[14];
    const float* lpb2 = (const float*)d_in[15];
    const float* Wih  = (const float*)d_in[16];
    const float* bih  = (const float*)d_in[17];
    // d_in[18] = gru_Whh (unused: h0 = 0)
    const float* bhh  = (const float*)d_in[19];
    const float* dec1 = (const float*)d_in[20];
    const float* decb1= (const float*)d_in[21];
    const float* dec2 = (const float*)d_in[22];
    const float* decb2= (const float*)d_in[23];
    float* out = (float*)d_out;

    const int gmm_smem = 29184 + 128;   // 29312 bytes
    cudaFuncSetAttribute(k_gmm, cudaFuncAttributeMaxDynamicSharedMemorySize, gmm_smem);

    k_cp<<<(EE + 255) / 256, 256>>>(ei, ea, Wih, bih, bhh,
                                    toW2, tob2, frW2, frb2, lpW2, lpb2,
                                    toW1, tob1, frW1, frb1);
    k_scansc<<<dim3(NB, 2), 1024>>>(ei, ea, lpW1, lpb1, x);

    int nblk = (NN + 127) / 128;
    for (int step = 0; step < 4; step++) {
        int do_proj = (step < 3) ? 1 : 0;
        k_pass<<<6250, 256>>>();
        k_gmm<<<nblk, 256, gmm_smem>>>(bhh);
        dim3 pgrid(nblk, do_proj ? 4 : 1);
        k_post<<<pgrid, 128>>>(toW1, frW1, lpW1, lpb1, dec1, decb1, dec2, decb2, y,
                               (step == 3) ? out : nullptr, step);
    }
    k_final<<<1024, 256>>>(out);
}